// round 12
// baseline (speedup 1.0000x reference)
#include <cuda_runtime.h>
#include <cuda_fp16.h>
#include <cstdint>
#include <cstddef>

#define NN 20000
#define FEAT 512
#define FF (FEAT*FEAT)
#define EE 320000
#define EPS 1e-5f
#define GY ((NN + 127) / 128)

// ---------------- scratch (device globals; no allocation allowed) ----------------
__device__ float  g_x[2][NN*FEAT];                 // fp32 GEMM outputs (BN input)
__device__ __half g_h16[2][(size_t)NN*FEAT];       // fp16 node feats (GEMM A + gather source)
__device__ __half g_m16[8][(size_t)NN*FEAT];       // fp16 aggregate means (L0: 0-3, L1: 4-7)
__device__ __half g_w16[14][(size_t)FF];           // fp16 weights
__device__ float  g_bsum[2][FEAT];
__device__ float  g_stats[8*FEAT];
__device__ int    g_cnt[4][NN];
__device__ int    g_off[4][NN+1];
__device__ int    g_cur[4][NN];
__device__ int    g_srcid[4][EE];

// ---------------- small utils ----------------
__global__ void k_zero_int(int* p, int n) {
    int i = blockIdx.x*blockDim.x + threadIdx.x;
    if (i < n) p[i] = 0;
}
__global__ void k_zero_float(float* p, int n) {
    int i = blockIdx.x*blockDim.x + threadIdx.x;
    if (i < n) p[i] = 0.f;
}

// ---------------- CSR build ----------------
__global__ void k_count(const int* __restrict__ a_src, const int* __restrict__ a_dst,
                        const int* __restrict__ i_src, const int* __restrict__ i_dst, int e) {
    int idx = blockIdx.x*blockDim.x + threadIdx.x;
    if (idx >= e) return;
    atomicAdd(&g_cnt[0][a_dst[idx]], 1);
    atomicAdd(&g_cnt[1][a_src[idx]], 1);
    atomicAdd(&g_cnt[2][i_dst[idx]], 1);
    atomicAdd(&g_cnt[3][i_src[idx]], 1);
}

__global__ void k_scan() {
    int r = blockIdx.x;
    int t = threadIdx.x;
    const int per = (NN + 1023) / 1024;
    __shared__ int part[1024];
    int base = t * per;
    int sum = 0;
    for (int i = 0; i < per; i++) { int idx = base + i; if (idx < NN) sum += g_cnt[r][idx]; }
    part[t] = sum;
    __syncthreads();
    for (int d = 1; d < 1024; d <<= 1) {
        int v = 0;
        if (t >= d) v = part[t-d];
        __syncthreads();
        if (t >= d) part[t] += v;
        __syncthreads();
    }
    int run = (t == 0) ? 0 : part[t-1];
    for (int i = 0; i < per; i++) {
        int idx = base + i;
        if (idx < NN) { g_off[r][idx] = run; g_cur[r][idx] = run; run += g_cnt[r][idx]; }
    }
    if (t == 1023) g_off[r][NN] = run;
}

__global__ void k_fill(const int* __restrict__ a_src, const int* __restrict__ a_dst,
                       const int* __restrict__ i_src, const int* __restrict__ i_dst, int e) {
    int idx = blockIdx.x*blockDim.x + threadIdx.x;
    if (idx >= e) return;
    int p;
    p = atomicAdd(&g_cur[0][a_dst[idx]], 1); g_srcid[0][p] = a_src[idx];
    p = atomicAdd(&g_cur[1][a_src[idx]], 1); g_srcid[1][p] = a_dst[idx];
    p = atomicAdd(&g_cur[2][i_dst[idx]], 1); g_srcid[2][p] = i_src[idx];
    p = atomicAdd(&g_cur[3][i_src[idx]], 1); g_srcid[3][p] = i_dst[idx];
}

// ---------------- conversions ----------------
// grid.y = which tensor (0: p, 1: d)
__global__ void k_toF16x2(__half* __restrict__ d0, const float* __restrict__ s0,
                          __half* __restrict__ d1, const float* __restrict__ s1, int M) {
    __half* dst = blockIdx.y ? d1 : d0;
    const float* src = blockIdx.y ? s1 : s0;
    int i = blockIdx.x*blockDim.x + threadIdx.x;
    if (i >= M*128) return;
    int r = i >> 7, c = (i & 127) * 4;
    float4 v = *(const float4*)(src + (size_t)r*FEAT + c);
    __half2 p0 = __halves2half2(__float2half_rn(v.x), __float2half_rn(v.y));
    __half2 p1 = __halves2half2(__float2half_rn(v.z), __float2half_rn(v.w));
    *(__half2*)(dst + (size_t)r*FEAT + c)     = p0;
    *(__half2*)(dst + (size_t)r*FEAT + c + 2) = p1;
}

struct WJobs { const float* src[12]; __half* dst[12]; };
__global__ void k_w12(WJobs jobs) {
    int slot = blockIdx.y;
    int i = blockIdx.x*blockDim.x + threadIdx.x;
    if (i >= FF/2) return;
    const float2 v = *(const float2*)(jobs.src[slot] + 2*(size_t)i);
    __half2 h = __halves2half2(__float2half_rn(v.x), __float2half_rn(v.y));
    *(__half2*)(jobs.dst[slot] + 2*(size_t)i) = h;
}

// Wsum = Ws[0]+Ws[2]+Ws[3] (to fp16); bsum = b[0]+b[2]+b[3]
__global__ void k_combine16(__half* __restrict__ dst,
                            const float* __restrict__ Ws, const float* __restrict__ b,
                            float* __restrict__ bsum) {
    int i = blockIdx.x*blockDim.x + threadIdx.x;
    if (i < FF) {
        float x = Ws[i] + Ws[2*(size_t)FF + i] + Ws[3*(size_t)FF + i];
        dst[i] = __float2half_rn(x);
    }
    if (i < FEAT) bsum[i] = b[i] + b[2*FEAT + i] + b[3*FEAT + i];
}

// ---------------- aggregation (fp16 gather, fp32 accumulate, fp16 out) ----------------
__global__ void k_aggregate(__half* __restrict__ outh, const __half* __restrict__ hsrc, int rel) {
    int node = blockIdx.x;
    int t = threadIdx.x;  // 0..127
    int beg = g_off[rel][node];
    int end = g_off[rel][node+1];
    float ax = 0.f, ay = 0.f, az = 0.f, aw = 0.f;
    int j = beg;
    for (; j + 1 < end; j += 2) {
        int s0 = g_srcid[rel][j];
        int s1 = g_srcid[rel][j+1];
        uint2 v0 = __ldg((const uint2*)(hsrc + (size_t)s0*FEAT) + t);
        uint2 v1 = __ldg((const uint2*)(hsrc + (size_t)s1*FEAT) + t);
        float2 a0 = __half22float2(*(__half2*)&v0.x);
        float2 a1 = __half22float2(*(__half2*)&v0.y);
        float2 b0 = __half22float2(*(__half2*)&v1.x);
        float2 b1 = __half22float2(*(__half2*)&v1.y);
        ax += a0.x + b0.x; ay += a0.y + b0.y;
        az += a1.x + b1.x; aw += a1.y + b1.y;
    }
    if (j < end) {
        int s = g_srcid[rel][j];
        uint2 v = __ldg((const uint2*)(hsrc + (size_t)s*FEAT) + t);
        float2 f0 = __half22float2(*(__half2*)&v.x);
        float2 f1 = __half22float2(*(__half2*)&v.y);
        ax += f0.x; ay += f0.y; az += f1.x; aw += f1.y;
    }
    float inv = (end > beg) ? 1.f / (float)(end - beg) : 0.f;
    __half2 p0 = __halves2half2(__float2half_rn(ax*inv), __float2half_rn(ay*inv));
    __half2 p1 = __halves2half2(__float2half_rn(az*inv), __float2half_rn(aw*inv));
    size_t base = (size_t)node*FEAT + t*4;
    *(__half2*)(outh + base)     = p0;
    *(__half2*)(outh + base + 2) = p1;
}

// ---------------- fp16 tensor-core GEMM (multi-segment, 3-stage pipeline) ----------------
struct Segs {
    const __half* a[4];
    const __half* w[4];
    int n;
};

__device__ __forceinline__ uint32_t sptr(const void* p) {
    return (uint32_t)__cvta_generic_to_shared(p);
}
__device__ __forceinline__ void cpa16(uint32_t sa, const void* g, bool pred) {
    int sz = pred ? 16 : 0;
    asm volatile("cp.async.cg.shared.global [%0], [%1], 16, %2;\n" :: "r"(sa), "l"(g), "r"(sz));
}

#define APAD 40
#define BPAD 136
#define A_ELEMS (128*APAD)
#define B_ELEMS (32*BPAD)
#define STG_ELEMS (A_ELEMS + B_ELEMS)
#define OFF_A(buf) ((buf)*STG_ELEMS)
#define OFF_B(buf) ((buf)*STG_ELEMS + A_ELEMS)
#define SMEM_ELEMS (3*STG_ELEMS)
#define SMEM_BYTES (SMEM_ELEMS*2)

__global__ __launch_bounds__(256)
void k_mma2(const Segs segs, const float* __restrict__ bias, float* __restrict__ C,
            float* __restrict__ stats, int M, int accum)
{
    extern __shared__ __align__(16) __half sm[];

    const int tid  = threadIdx.x;
    const int lane = tid & 31;
    const int warp = tid >> 5;
    const int wm = (warp & 1) * 64;      // 2 warps along M
    const int wn = (warp >> 1) * 32;     // 4 warps along N
    const int row0 = blockIdx.y * 128;
    const int col0 = blockIdx.x * 128;

    float acc[4][4][4];
    #pragma unroll
    for (int i = 0; i < 4; i++)
        #pragma unroll
        for (int j = 0; j < 4; j++)
            #pragma unroll
            for (int k = 0; k < 4; k++) acc[i][j][k] = 0.f;

    const int T = segs.n * 16;

    auto issue = [&](int t) {
        int buf = t % 3;
        int s  = t >> 4;
        int k0 = (t & 15) * 32;
        const __half* A = segs.a[s];
        const __half* W = segs.w[s];
        #pragma unroll
        for (int l = 0; l < 2; l++) {
            int idx = tid + l*256;       // 0..511
            int r  = idx >> 2;           // 0..127
            int c  = (idx & 3) * 8;      // 0,8,16,24
            int gr = row0 + r;
            cpa16(sptr(sm + OFF_A(buf) + r*APAD + c), A + (size_t)gr*FEAT + k0 + c, gr < M);
            int br = idx >> 4;           // 0..31
            int bc = (idx & 15) * 8;     // 0..120
            cpa16(sptr(sm + OFF_B(buf) + br*BPAD + bc), W + (size_t)(k0 + br)*512 + col0 + bc, true);
        }
        asm volatile("cp.async.commit_group;\n" ::: "memory");
    };

    issue(0);
    if (T > 1) issue(1);

    const int g2 = lane >> 3, lr = lane & 7;

    for (int t = 0; t < T; t++) {
        int buf = t % 3;
        if (t + 1 < T) asm volatile("cp.async.wait_group 1;\n" ::: "memory");
        else           asm volatile("cp.async.wait_group 0;\n" ::: "memory");
        __syncthreads();
        if (t + 2 < T) issue(t + 2);

        #pragma unroll
        for (int ks = 0; ks < 2; ks++) {
            int arow = wm + (g2 & 1)*8 + lr;
            int acol = ks*16 + (g2 >> 1)*8;
            uint32_t af[4][4];
            #pragma unroll
            for (int mi = 0; mi < 4; mi++) {
                uint32_t ad = sptr(sm + OFF_A(buf) + (arow + mi*16)*APAD + acol);
                asm volatile("ldmatrix.sync.aligned.m8n8.x4.shared.b16 {%0,%1,%2,%3}, [%4];\n"
                    : "=r"(af[mi][0]), "=r"(af[mi][1]), "=r"(af[mi][2]), "=r"(af[mi][3])
                    : "r"(ad));
            }
            int brow = ks*16 + (g2 & 1)*8 + lr;
            uint32_t bf[2][4];
            #pragma unroll
            for (int nj = 0; nj < 2; nj++) {
                int bcol = wn + nj*16 + (g2 >> 1)*8;
                uint32_t bd = sptr(sm + OFF_B(buf) + brow*BPAD + bcol);
                asm volatile("ldmatrix.sync.aligned.m8n8.x4.trans.shared.b16 {%0,%1,%2,%3}, [%4];\n"
                    : "=r"(bf[nj][0]), "=r"(bf[nj][1]), "=r"(bf[nj][2]), "=r"(bf[nj][3])
                    : "r"(bd));
            }
            #pragma unroll
            for (int mi = 0; mi < 4; mi++)
                #pragma unroll
                for (int ni = 0; ni < 4; ni++) {
                    uint32_t b0 = bf[ni >> 1][(ni & 1)*2];
                    uint32_t b1 = bf[ni >> 1][(ni & 1)*2 + 1];
                    asm volatile(
                        "mma.sync.aligned.m16n8k16.row.col.f32.f16.f16.f32 "
                        "{%0,%1,%2,%3}, {%4,%5,%6,%7}, {%8,%9}, {%0,%1,%2,%3};\n"
                        : "+f"(acc[mi][ni][0]), "+f"(acc[mi][ni][1]),
                          "+f"(acc[mi][ni][2]), "+f"(acc[mi][ni][3])
                        : "r"(af[mi][0]), "r"(af[mi][1]), "r"(af[mi][2]), "r"(af[mi][3]),
                          "r"(b0), "r"(b1));
                }
        }
    }

    // epilogue: (accumulate|bias) + store + optional fused column stats
    float vsum[4][2], vsq[4][2];
    #pragma unroll
    for (int ni = 0; ni < 4; ni++) { vsum[ni][0]=vsum[ni][1]=vsq[ni][0]=vsq[ni][1]=0.f; }

    #pragma unroll
    for (int mi = 0; mi < 4; mi++) {
        int gr0 = row0 + wm + mi*16 + (lane >> 2);
        int gr1 = gr0 + 8;
        bool p0 = gr0 < M, p1 = gr1 < M;
        #pragma unroll
        for (int ni = 0; ni < 4; ni++) {
            int gc = col0 + wn + ni*8 + (lane & 3)*2;
            float a00 = acc[mi][ni][0], a01 = acc[mi][ni][1];
            float a10 = acc[mi][ni][2], a11 = acc[mi][ni][3];
            if (accum) {
                if (p0) {
                    float2 c0 = *(float2*)(C + (size_t)gr0*FEAT + gc);
                    a00 += c0.x; a01 += c0.y;
                }
                if (p1) {
                    float2 c1 = *(float2*)(C + (size_t)gr1*FEAT + gc);
                    a10 += c1.x; a11 += c1.y;
                }
            } else {
                float b0 = bias[gc], b1 = bias[gc+1];
                a00 += b0; a01 += b1; a10 += b0; a11 += b1;
            }
            if (p0) {
                float2 o; o.x = a00; o.y = a01;
                *(float2*)(C + (size_t)gr0*FEAT + gc) = o;
                vsum[ni][0] += a00; vsq[ni][0] += a00*a00;
                vsum[ni][1] += a01; vsq[ni][1] += a01*a01;
            }
            if (p1) {
                float2 o; o.x = a10; o.y = a11;
                *(float2*)(C + (size_t)gr1*FEAT + gc) = o;
                vsum[ni][0] += a10; vsq[ni][0] += a10*a10;
                vsum[ni][1] += a11; vsq[ni][1] += a11*a11;
            }
        }
    }

    if (stats) {
        #pragma unroll
        for (int ni = 0; ni < 4; ni++) {
            #pragma unroll
            for (int j = 0; j < 2; j++) {
                float s = vsum[ni][j], q = vsq[ni][j];
                #pragma unroll
                for (int st = 4; st < 32; st <<= 1) {
                    s += __shfl_xor_sync(0xFFFFFFFFu, s, st);
                    q += __shfl_xor_sync(0xFFFFFFFFu, q, st);
                }
                if (lane < 4) {
                    int c = col0 + wn + ni*8 + lane*2 + j;
                    atomicAdd(&stats[c], s);
                    atomicAdd(&stats[FEAT + c], q);
                }
            }
        }
    }
}

// ---------------- BatchNorm (apply): fp32 in -> fp16 out ----------------
__global__ void k_bnrelu(const float* __restrict__ X, __half* __restrict__ X16,
                         const float* __restrict__ stats,
                         const float* __restrict__ gamma, const float* __restrict__ beta, int M) {
    int i = blockIdx.x*blockDim.x + threadIdx.x;
    if (i >= M*128) return;
    int r = i >> 7, c = (i & 127) * 4;
    float invM = 1.f / (float)M;
    float4 x = *(const float4*)(X + (size_t)r*FEAT + c);
    float xv[4] = {x.x, x.y, x.z, x.w};
    float y[4];
    #pragma unroll
    for (int j = 0; j < 4; j++) {
        int cc = c + j;
        float mean = stats[cc] * invM;
        float var  = stats[FEAT + cc] * invM - mean*mean;
        float v = gamma[cc] * (xv[j] - mean) * rsqrtf(var + EPS) + beta[cc];
        y[j] = v > 0.f ? v : 0.f;
    }
    __half2 p0 = __halves2half2(__float2half_rn(y[0]), __float2half_rn(y[1]));
    __half2 p1 = __halves2half2(__float2half_rn(y[2]), __float2half_rn(y[3]));
    *(__half2*)(X16 + (size_t)r*FEAT + c)     = p0;
    *(__half2*)(X16 + (size_t)r*FEAT + c + 2) = p1;
}

// ---------------- host ----------------
static void* sym(const void* s) { void* p = nullptr; cudaGetSymbolAddress(&p, s); return p; }

struct StreamCtx {
    cudaStream_t s1;
    cudaEvent_t ev[10];
    bool ok;
    StreamCtx() {
        ok = (cudaStreamCreateWithFlags(&s1, cudaStreamNonBlocking) == cudaSuccess);
        for (int i = 0; i < 10; i++)
            if (cudaEventCreateWithFlags(&ev[i], cudaEventDisableTiming) != cudaSuccess) ok = false;
    }
};

enum { E_START=0, E_X16, E_M1, E_PSELF, E_BND0, E_BNP0, E_M4, E_M5, E_S1 };

extern "C" void kernel_launch(void* const* d_in, const int* in_sizes, int n_in,
                              void* d_out, int out_size)
{
    static StreamCtx ctx;

    const float* h_d  = (const float*)d_in[0];
    const float* h_p  = (const float*)d_in[1];
    const float* Ws1  = (const float*)d_in[2];
    const float* Wn1  = (const float*)d_in[3];
    const float* b1   = (const float*)d_in[4];
    const float* Ws2  = (const float*)d_in[5];
    const float* Wn2  = (const float*)d_in[6];
    const float* b2   = (const float*)d_in[7];
    const float* gam  = (const float*)d_in[8];
    const float* bet  = (const float*)d_in[9];
    const float* pWd  = (const float*)d_in[10];
    const float* pbd  = (const float*)d_in[11];
    const float* pWp  = (const float*)d_in[12];
    const float* pbp  = (const float*)d_in[13];
    const int*  a_src = (const int*)d_in[14];
    const int*  a_dst = (const int*)d_in[15];
    const int*  i_src = (const int*)d_in[16];
    const int*  i_dst = (const int*)d_in[17];
    float* out = (float*)d_out;
    const int e = in_sizes[14];

    float* xd    = (float*)sym(g_x);
    float* xp    = xd + (size_t)NN*FEAT;
    __half* h16d = (__half*)sym(g_h16);
    __half* h16p = h16d + (size_t)NN*FEAT;
    __half* m16  = (__half*)sym(g_m16);
    auto Mb = [&](int slot) { return m16 + (size_t)slot * NN * FEAT; };
    __half* w16  = (__half*)sym(g_w16);
    auto W = [&](int slot) { return w16 + (size_t)slot * FF; };
    float* bsum0 = (float*)sym(g_bsum);
    float* bsum1 = bsum0 + FEAT;
    float* st    = (float*)sym(g_stats);
    float* st0d = st, *st0p = st + 2*FEAT, *st1d = st + 4*FEAT, *st1p = st + 6*FEAT;
    int*   cnt   = (int*)sym(g_cnt);

    cudaFuncSetAttribute(k_mma2, cudaFuncAttributeMaxDynamicSharedMemorySize, SMEM_BYTES);

    const bool ok = ctx.ok;
    cudaStream_t S0 = 0;
    cudaStream_t S1 = ok ? ctx.s1 : (cudaStream_t)0;
    auto rec  = [&](int i, cudaStream_t s) { if (ok) cudaEventRecord(ctx.ev[i], s); };
    auto wait = [&](cudaStream_t s, int i)  { if (ok) cudaStreamWaitEvent(s, ctx.ev[i], 0); };

    int xgrid = (NN*128 + 255)/256;
    int wgrid = (FF + 255)/256;
    dim3 ggrid(4, GY);

    auto gemm = [&](cudaStream_t s, const __half* A0, const __half* W0,
                    const float* bias, float* C, float* stats, int accum,
                    const __half* A1 = nullptr, const __half* W1 = nullptr,
                    const __half* A2 = nullptr, const __half* W2p = nullptr) {
        Segs t; t.n = 1;
        t.a[0] = A0; t.w[0] = W0;
        if (A1) { t.a[t.n] = A1; t.w[t.n] = W1; t.n++; }
        if (A2) { t.a[t.n] = A2; t.w[t.n] = W2p; t.n++; }
        k_mma2<<<ggrid, 256, SMEM_BYTES, s>>>(t, bias, C, stats, NN, accum);
    };

    // fork
    rec(E_START, S0);
    wait(S1, E_START);

    // ---- S0: CSR build ----
    k_zero_int<<<(4*NN + 255)/256, 256, 0, S0>>>(cnt, 4*NN);
    k_count<<<(e + 255)/256, 256, 0, S0>>>(a_src, a_dst, i_src, i_dst, e);
    k_scan<<<4, 1024, 0, S0>>>();
    k_fill<<<(e + 255)/256, 256, 0, S0>>>(a_src, a_dst, i_src, i_dst, e);

    // ---- S1: fp16 input conversions ----
    {
        dim3 cg(xgrid, 2);
        k_toF16x2<<<cg, 256, 0, S1>>>(h16p, h_p, h16d, h_d, NN);
    }
    rec(E_X16, S1);

    // ---- S0: layer0 aggregates (m0..m3) ----
    wait(S0, E_X16);
    k_aggregate<<<NN, 128, 0, S0>>>(Mb(1), h16p, 1);
    rec(E_M1, S0);
    k_aggregate<<<NN, 128, 0, S0>>>(Mb(0), h16d, 0);
    k_aggregate<<<NN, 128, 0, S0>>>(Mb(2), h16p, 2);
    k_aggregate<<<NN, 128, 0, S0>>>(Mb(3), h16p, 3);

    // ---- S1: weight conversions + stats zero ----
    k_combine16<<<wgrid, 256, 0, S1>>>(W(2), Ws1, b1, bsum0);
    k_combine16<<<wgrid, 256, 0, S1>>>(W(8), Ws2, b2, bsum1);
    {
        WJobs jb;
        jb.src[0] = Ws1 + (size_t)FF;     jb.dst[0] = W(0);
        jb.src[1] = Wn1 + (size_t)FF;     jb.dst[1] = W(1);
        jb.src[2] = Wn1;                  jb.dst[2] = W(3);
        jb.src[3] = Wn1 + 2*(size_t)FF;   jb.dst[3] = W(4);
        jb.src[4] = Wn1 + 3*(size_t)FF;   jb.dst[4] = W(5);
        jb.src[5] = Ws2 + (size_t)FF;     jb.dst[5] = W(6);
        jb.src[6] = Wn2 + (size_t)FF;     jb.dst[6] = W(7);
        jb.src[7] = Wn2;                  jb.dst[7] = W(9);
        jb.src[8] = Wn2 + 2*(size_t)FF;   jb.dst[8] = W(10);
        jb.src[9] = Wn2 + 3*(size_t)FF;   jb.dst[9] = W(11);
        jb.src[10] = pWd;                 jb.dst[10] = W(12);
        jb.src[11] = pWp;                 jb.dst[11] = W(13);
        dim3 wg((FF/2 + 255)/256, 12);
        k_w12<<<wg, 256, 0, S1>>>(jb);
    }
    k_zero_float<<<(8*FEAT + 255)/256, 256, 0, S1>>>(st, 8*FEAT);

    // ---- S1: layer0 self GEMMs ----
    gemm(S1, h16p, W(2), bsum0,     xp, nullptr, 0);         // protein self
    rec(E_PSELF, S1);
    gemm(S1, h16d, W(0), b1 + FEAT, xd, nullptr, 0);         // disease self

    // ---- S1: layer0 disease neigh + BN, then L1 disease self immediately ----
    wait(S1, E_M1);
    gemm(S1, m16 + (size_t)1*NN*FEAT, W(1), nullptr, xd, st0d, 1);
    k_bnrelu<<<xgrid, 256, 0, S1>>>(xd, h16d, st0d, gam + 0*FEAT, bet + 0*FEAT, NN);
    rec(E_BND0, S1);
    gemm(S1, h16d, W(6), b2 + FEAT, xd, nullptr, 0);         // L1 disease self (only needs BN_d0)

    // ---- S0: layer0 protein neigh + BN ----
    wait(S0, E_PSELF);
    gemm(S0, Mb(0), W(3), nullptr, xp, st0p, 1, Mb(2), W(4), Mb(3), W(5));
    k_bnrelu<<<xgrid, 256, 0, S0>>>(xp, h16p, st0p, gam + 1*FEAT, bet + 1*FEAT, NN);
    rec(E_BNP0, S0);

    // ---- S0: layer1 aggregates m4 (disease src), m6, m7 (protein src) ----
    wait(S0, E_BND0);
    k_aggregate<<<NN, 128, 0, S0>>>(Mb(4), h16d, 0);
    rec(E_M4, S0);
    k_aggregate<<<NN, 128, 0, S0>>>(Mb(6), h16p, 2);
    k_aggregate<<<NN, 128, 0, S0>>>(Mb(7), h16p, 3);

    // ---- S1: layer1 disease chain ----
    wait(S1, E_BNP0);
    k_aggregate<<<NN, 128, 0, S1>>>(Mb(5), h16p, 1);
    rec(E_M5, S1);
    gemm(S1, Mb(5), W(7), nullptr, xd, st1d, 1);
    wait(S1, E_M4);                   // h16d WAR: S0's m4 gather reads h16d before BN_d1 overwrites
    k_bnrelu<<<xgrid, 256, 0, S1>>>(xd, h16d, st1d, gam + 2*FEAT, bet + 2*FEAT, NN);
    gemm(S1, h16d, W(12), pbd, out, nullptr, 0);
    rec(E_S1, S1);

    // ---- S0: layer1 protein chain + projection ----
    gemm(S0, h16p, W(8), bsum1, xp, nullptr, 0);             // L1 protein self
    gemm(S0, Mb(4), W(9), nullptr, xp, st1p, 1, Mb(6), W(10), Mb(7), W(11));
    wait(S0, E_M5);                   // h16p WAR: S1's m5 gather reads h16p before BN_p1 overwrites
    k_bnrelu<<<xgrid, 256, 0, S0>>>(xp, h16p, st1p, gam + 3*FEAT, bet + 3*FEAT, NN);
    gemm(S0, h16p, W(13), pbp, out + (size_t)NN*FEAT, nullptr, 0);

    // join
    wait(S0, E_S1);
}

// round 14
// speedup vs baseline: 1.4979x; 1.4979x over previous
#include <cuda_runtime.h>
#include <cuda_fp16.h>
#include <cstdint>
#include <cstddef>

#define NN 20000
#define FEAT 512
#define FF (FEAT*FEAT)
#define EE 320000
#define EPS 1e-5f
#define GY ((NN + 127) / 128)

// ---------------- scratch (device globals; no allocation allowed) ----------------
__device__ float  g_x[2][NN*FEAT];                 // fp32 GEMM outputs (BN input)
__device__ __half g_h16[2][(size_t)NN*FEAT];       // fp16 node feats (GEMM A + gather source)
__device__ __half g_m16[4][(size_t)NN*FEAT];       // fp16 aggregate means
__device__ __half g_w16[14][(size_t)FF];           // fp16 weights
__device__ float  g_bsum[2][FEAT];
__device__ float  g_stats[8*FEAT];
__device__ int    g_cnt[4][NN];
__device__ int    g_off[4][NN+1];
__device__ int    g_cur[4][NN];
__device__ int    g_srcid[4][EE];

// ---------------- small utils ----------------
__global__ void k_zero_int(int* p, int n) {
    int i = blockIdx.x*blockDim.x + threadIdx.x;
    if (i < n) p[i] = 0;
}
__global__ void k_zero_float(float* p, int n) {
    int i = blockIdx.x*blockDim.x + threadIdx.x;
    if (i < n) p[i] = 0.f;
}

// ---------------- CSR build ----------------
__global__ void k_count(const int* __restrict__ a_src, const int* __restrict__ a_dst,
                        const int* __restrict__ i_src, const int* __restrict__ i_dst, int e) {
    int idx = blockIdx.x*blockDim.x + threadIdx.x;
    if (idx >= e) return;
    atomicAdd(&g_cnt[0][a_dst[idx]], 1);
    atomicAdd(&g_cnt[1][a_src[idx]], 1);
    atomicAdd(&g_cnt[2][i_dst[idx]], 1);
    atomicAdd(&g_cnt[3][i_src[idx]], 1);
}

__global__ void k_scan() {
    int r = blockIdx.x;
    int t = threadIdx.x;
    const int per = (NN + 1023) / 1024;
    __shared__ int part[1024];
    int base = t * per;
    int sum = 0;
    for (int i = 0; i < per; i++) { int idx = base + i; if (idx < NN) sum += g_cnt[r][idx]; }
    part[t] = sum;
    __syncthreads();
    for (int d = 1; d < 1024; d <<= 1) {
        int v = 0;
        if (t >= d) v = part[t-d];
        __syncthreads();
        if (t >= d) part[t] += v;
        __syncthreads();
    }
    int run = (t == 0) ? 0 : part[t-1];
    for (int i = 0; i < per; i++) {
        int idx = base + i;
        if (idx < NN) { g_off[r][idx] = run; g_cur[r][idx] = run; run += g_cnt[r][idx]; }
    }
    if (t == 1023) g_off[r][NN] = run;
}

__global__ void k_fill(const int* __restrict__ a_src, const int* __restrict__ a_dst,
                       const int* __restrict__ i_src, const int* __restrict__ i_dst, int e) {
    int idx = blockIdx.x*blockDim.x + threadIdx.x;
    if (idx >= e) return;
    int p;
    p = atomicAdd(&g_cur[0][a_dst[idx]], 1); g_srcid[0][p] = a_src[idx];
    p = atomicAdd(&g_cur[1][a_src[idx]], 1); g_srcid[1][p] = a_dst[idx];
    p = atomicAdd(&g_cur[2][i_dst[idx]], 1); g_srcid[2][p] = i_src[idx];
    p = atomicAdd(&g_cur[3][i_src[idx]], 1); g_srcid[3][p] = i_dst[idx];
}

// ---------------- conversions ----------------
// grid.y = which tensor (0: p, 1: d)
__global__ void k_toF16x2(__half* __restrict__ d0, const float* __restrict__ s0,
                          __half* __restrict__ d1, const float* __restrict__ s1, int M) {
    __half* dst = blockIdx.y ? d1 : d0;
    const float* src = blockIdx.y ? s1 : s0;
    int i = blockIdx.x*blockDim.x + threadIdx.x;
    if (i >= M*128) return;
    int r = i >> 7, c = (i & 127) * 4;
    float4 v = *(const float4*)(src + (size_t)r*FEAT + c);
    __half2 p0 = __halves2half2(__float2half_rn(v.x), __float2half_rn(v.y));
    __half2 p1 = __halves2half2(__float2half_rn(v.z), __float2half_rn(v.w));
    *(__half2*)(dst + (size_t)r*FEAT + c)     = p0;
    *(__half2*)(dst + (size_t)r*FEAT + c + 2) = p1;
}

struct WJobs { const float* src[12]; __half* dst[12]; };
__global__ void k_w12(WJobs jobs) {
    int slot = blockIdx.y;
    int i = blockIdx.x*blockDim.x + threadIdx.x;
    if (i >= FF/2) return;
    const float2 v = *(const float2*)(jobs.src[slot] + 2*(size_t)i);
    __half2 h = __halves2half2(__float2half_rn(v.x), __float2half_rn(v.y));
    *(__half2*)(jobs.dst[slot] + 2*(size_t)i) = h;
}

// Wsum = Ws[0]+Ws[2]+Ws[3] (to fp16); bsum = b[0]+b[2]+b[3]; grid.y = layer
__global__ void k_combine2(__half* __restrict__ dst0, const float* __restrict__ Ws0,
                           const float* __restrict__ b0, float* __restrict__ bsum0,
                           __half* __restrict__ dst1, const float* __restrict__ Ws1,
                           const float* __restrict__ b1, float* __restrict__ bsum1) {
    __half* dst = blockIdx.y ? dst1 : dst0;
    const float* Ws = blockIdx.y ? Ws1 : Ws0;
    const float* b  = blockIdx.y ? b1 : b0;
    float* bsum     = blockIdx.y ? bsum1 : bsum0;
    int i = blockIdx.x*blockDim.x + threadIdx.x;
    if (i < FF) {
        float x = Ws[i] + Ws[2*(size_t)FF + i] + Ws[3*(size_t)FF + i];
        dst[i] = __float2half_rn(x);
    }
    if (i < FEAT) bsum[i] = b[i] + b[2*FEAT + i] + b[3*FEAT + i];
}

// ---------------- aggregation (fp16 gather, fp32 accumulate, fp16 out) ----------------
__global__ void k_aggregate(__half* __restrict__ outh, const __half* __restrict__ hsrc, int rel) {
    int node = blockIdx.x;
    int t = threadIdx.x;  // 0..127
    int beg = g_off[rel][node];
    int end = g_off[rel][node+1];
    float ax = 0.f, ay = 0.f, az = 0.f, aw = 0.f;
    for (int j = beg; j < end; j++) {
        int s = g_srcid[rel][j];
        uint2 v = __ldg((const uint2*)(hsrc + (size_t)s*FEAT) + t);
        __half2 h0 = *(__half2*)&v.x;
        __half2 h1 = *(__half2*)&v.y;
        float2 f0 = __half22float2(h0);
        float2 f1 = __half22float2(h1);
        ax += f0.x; ay += f0.y; az += f1.x; aw += f1.y;
    }
    float inv = (end > beg) ? 1.f / (float)(end - beg) : 0.f;
    __half2 p0 = __halves2half2(__float2half_rn(ax*inv), __float2half_rn(ay*inv));
    __half2 p1 = __halves2half2(__float2half_rn(az*inv), __float2half_rn(aw*inv));
    size_t base = (size_t)node*FEAT + t*4;
    *(__half2*)(outh + base)     = p0;
    *(__half2*)(outh + base + 2) = p1;
}

// ---------------- fp16 tensor-core GEMM (multi-segment, 3-stage pipeline) ----------------
struct Segs {
    const __half* a[4];
    const __half* w[4];
    int n;
};

__device__ __forceinline__ uint32_t sptr(const void* p) {
    return (uint32_t)__cvta_generic_to_shared(p);
}
__device__ __forceinline__ void cpa16(uint32_t sa, const void* g, bool pred) {
    int sz = pred ? 16 : 0;
    asm volatile("cp.async.cg.shared.global [%0], [%1], 16, %2;\n" :: "r"(sa), "l"(g), "r"(sz));
}

#define APAD 40
#define BPAD 136
#define A_ELEMS (128*APAD)
#define B_ELEMS (32*BPAD)
#define STG_ELEMS (A_ELEMS + B_ELEMS)
#define OFF_A(buf) ((buf)*STG_ELEMS)
#define OFF_B(buf) ((buf)*STG_ELEMS + A_ELEMS)
#define SMEM_ELEMS (3*STG_ELEMS)
#define SMEM_BYTES (SMEM_ELEMS*2)

__global__ __launch_bounds__(256)
void k_mma2(const Segs segs, const float* __restrict__ bias, float* __restrict__ C,
            float* __restrict__ stats, int M, int accum)
{
    extern __shared__ __align__(16) __half sm[];

    const int tid  = threadIdx.x;
    const int lane = tid & 31;
    const int warp = tid >> 5;
    const int wm = (warp & 1) * 64;      // 2 warps along M
    const int wn = (warp >> 1) * 32;     // 4 warps along N
    const int row0 = blockIdx.y * 128;
    const int col0 = blockIdx.x * 128;

    float acc[4][4][4];
    #pragma unroll
    for (int i = 0; i < 4; i++)
        #pragma unroll
        for (int j = 0; j < 4; j++)
            #pragma unroll
            for (int k = 0; k < 4; k++) acc[i][j][k] = 0.f;

    const int T = segs.n * 16;

    auto issue = [&](int t) {
        int buf = t % 3;
        int s  = t >> 4;
        int k0 = (t & 15) * 32;
        const __half* A = segs.a[s];
        const __half* W = segs.w[s];
        #pragma unroll
        for (int l = 0; l < 2; l++) {
            int idx = tid + l*256;       // 0..511
            int r  = idx >> 2;           // 0..127
            int c  = (idx & 3) * 8;      // 0,8,16,24
            int gr = row0 + r;
            cpa16(sptr(sm + OFF_A(buf) + r*APAD + c), A + (size_t)gr*FEAT + k0 + c, gr < M);
            int br = idx >> 4;           // 0..31
            int bc = (idx & 15) * 8;     // 0..120
            cpa16(sptr(sm + OFF_B(buf) + br*BPAD + bc), W + (size_t)(k0 + br)*512 + col0 + bc, true);
        }
        asm volatile("cp.async.commit_group;\n" ::: "memory");
    };

    issue(0);
    if (T > 1) issue(1);

    const int g2 = lane >> 3, lr = lane & 7;

    for (int t = 0; t < T; t++) {
        int buf = t % 3;
        if (t + 1 < T) asm volatile("cp.async.wait_group 1;\n" ::: "memory");
        else           asm volatile("cp.async.wait_group 0;\n" ::: "memory");
        __syncthreads();
        if (t + 2 < T) issue(t + 2);

        #pragma unroll
        for (int ks = 0; ks < 2; ks++) {
            int arow = wm + (g2 & 1)*8 + lr;
            int acol = ks*16 + (g2 >> 1)*8;
            uint32_t af[4][4];
            #pragma unroll
            for (int mi = 0; mi < 4; mi++) {
                uint32_t ad = sptr(sm + OFF_A(buf) + (arow + mi*16)*APAD + acol);
                asm volatile("ldmatrix.sync.aligned.m8n8.x4.shared.b16 {%0,%1,%2,%3}, [%4];\n"
                    : "=r"(af[mi][0]), "=r"(af[mi][1]), "=r"(af[mi][2]), "=r"(af[mi][3])
                    : "r"(ad));
            }
            int brow = ks*16 + (g2 & 1)*8 + lr;
            uint32_t bf[2][4];
            #pragma unroll
            for (int nj = 0; nj < 2; nj++) {
                int bcol = wn + nj*16 + (g2 >> 1)*8;
                uint32_t bd = sptr(sm + OFF_B(buf) + brow*BPAD + bcol);
                asm volatile("ldmatrix.sync.aligned.m8n8.x4.trans.shared.b16 {%0,%1,%2,%3}, [%4];\n"
                    : "=r"(bf[nj][0]), "=r"(bf[nj][1]), "=r"(bf[nj][2]), "=r"(bf[nj][3])
                    : "r"(bd));
            }
            #pragma unroll
            for (int mi = 0; mi < 4; mi++)
                #pragma unroll
                for (int ni = 0; ni < 4; ni++) {
                    uint32_t b0 = bf[ni >> 1][(ni & 1)*2];
                    uint32_t b1 = bf[ni >> 1][(ni & 1)*2 + 1];
                    asm volatile(
                        "mma.sync.aligned.m16n8k16.row.col.f32.f16.f16.f32 "
                        "{%0,%1,%2,%3}, {%4,%5,%6,%7}, {%8,%9}, {%0,%1,%2,%3};\n"
                        : "+f"(acc[mi][ni][0]), "+f"(acc[mi][ni][1]),
                          "+f"(acc[mi][ni][2]), "+f"(acc[mi][ni][3])
                        : "r"(af[mi][0]), "r"(af[mi][1]), "r"(af[mi][2]), "r"(af[mi][3]),
                          "r"(b0), "r"(b1));
                }
        }
    }

    // epilogue: (accumulate|bias) + store + optional fused column stats
    float vsum[4][2], vsq[4][2];
    #pragma unroll
    for (int ni = 0; ni < 4; ni++) { vsum[ni][0]=vsum[ni][1]=vsq[ni][0]=vsq[ni][1]=0.f; }

    #pragma unroll
    for (int mi = 0; mi < 4; mi++) {
        int gr0 = row0 + wm + mi*16 + (lane >> 2);
        int gr1 = gr0 + 8;
        bool p0 = gr0 < M, p1 = gr1 < M;
        #pragma unroll
        for (int ni = 0; ni < 4; ni++) {
            int gc = col0 + wn + ni*8 + (lane & 3)*2;
            float a00 = acc[mi][ni][0], a01 = acc[mi][ni][1];
            float a10 = acc[mi][ni][2], a11 = acc[mi][ni][3];
            if (accum) {
                if (p0) {
                    float2 c0 = *(float2*)(C + (size_t)gr0*FEAT + gc);
                    a00 += c0.x; a01 += c0.y;
                }
                if (p1) {
                    float2 c1 = *(float2*)(C + (size_t)gr1*FEAT + gc);
                    a10 += c1.x; a11 += c1.y;
                }
            } else {
                float b0 = bias[gc], b1 = bias[gc+1];
                a00 += b0; a01 += b1; a10 += b0; a11 += b1;
            }
            if (p0) {
                float2 o; o.x = a00; o.y = a01;
                *(float2*)(C + (size_t)gr0*FEAT + gc) = o;
                vsum[ni][0] += a00; vsq[ni][0] += a00*a00;
                vsum[ni][1] += a01; vsq[ni][1] += a01*a01;
            }
            if (p1) {
                float2 o; o.x = a10; o.y = a11;
                *(float2*)(C + (size_t)gr1*FEAT + gc) = o;
                vsum[ni][0] += a10; vsq[ni][0] += a10*a10;
                vsum[ni][1] += a11; vsq[ni][1] += a11*a11;
            }
        }
    }

    if (stats) {
        #pragma unroll
        for (int ni = 0; ni < 4; ni++) {
            #pragma unroll
            for (int j = 0; j < 2; j++) {
                float s = vsum[ni][j], q = vsq[ni][j];
                #pragma unroll
                for (int st = 4; st < 32; st <<= 1) {
                    s += __shfl_xor_sync(0xFFFFFFFFu, s, st);
                    q += __shfl_xor_sync(0xFFFFFFFFu, q, st);
                }
                if (lane < 4) {
                    int c = col0 + wn + ni*8 + lane*2 + j;
                    atomicAdd(&stats[c], s);
                    atomicAdd(&stats[FEAT + c], q);
                }
            }
        }
    }
}

// ---------------- BatchNorm (apply): fp32 in -> fp16 out ----------------
__global__ void k_bnrelu(const float* __restrict__ X, __half* __restrict__ X16,
                         const float* __restrict__ stats,
                         const float* __restrict__ gamma, const float* __restrict__ beta, int M) {
    int i = blockIdx.x*blockDim.x + threadIdx.x;
    if (i >= M*128) return;
    int r = i >> 7, c = (i & 127) * 4;
    float invM = 1.f / (float)M;
    float4 x = *(const float4*)(X + (size_t)r*FEAT + c);
    float xv[4] = {x.x, x.y, x.z, x.w};
    float y[4];
    #pragma unroll
    for (int j = 0; j < 4; j++) {
        int cc = c + j;
        float mean = stats[cc] * invM;
        float var  = stats[FEAT + cc] * invM - mean*mean;
        float v = gamma[cc] * (xv[j] - mean) * rsqrtf(var + EPS) + beta[cc];
        y[j] = v > 0.f ? v : 0.f;
    }
    __half2 p0 = __halves2half2(__float2half_rn(y[0]), __float2half_rn(y[1]));
    __half2 p1 = __halves2half2(__float2half_rn(y[2]), __float2half_rn(y[3]));
    *(__half2*)(X16 + (size_t)r*FEAT + c)     = p0;
    *(__half2*)(X16 + (size_t)r*FEAT + c + 2) = p1;
}

// ---------------- host ----------------
static void* sym(const void* s) { void* p = nullptr; cudaGetSymbolAddress(&p, s); return p; }

struct StreamCtx {
    cudaStream_t s1;
    cudaEvent_t ev[10];
    bool ok;
    StreamCtx() {
        ok = (cudaStreamCreateWithFlags(&s1, cudaStreamNonBlocking) == cudaSuccess);
        for (int i = 0; i < 10; i++)
            if (cudaEventCreateWithFlags(&ev[i], cudaEventDisableTiming) != cudaSuccess) ok = false;
    }
};

enum { E_START=0, E_X16, E_M1, E_PSELF, E_BND0, E_BNP0, E_M0P, E_M1P, E_S1 };

extern "C" void kernel_launch(void* const* d_in, const int* in_sizes, int n_in,
                              void* d_out, int out_size)
{
    static StreamCtx ctx;

    const float* h_d  = (const float*)d_in[0];
    const float* h_p  = (const float*)d_in[1];
    const float* Ws1  = (const float*)d_in[2];
    const float* Wn1  = (const float*)d_in[3];
    const float* b1   = (const float*)d_in[4];
    const float* Ws2  = (const float*)d_in[5];
    const float* Wn2  = (const float*)d_in[6];
    const float* b2   = (const float*)d_in[7];
    const float* gam  = (const float*)d_in[8];
    const float* bet  = (const float*)d_in[9];
    const float* pWd  = (const float*)d_in[10];
    const float* pbd  = (const float*)d_in[11];
    const float* pWp  = (const float*)d_in[12];
    const float* pbp  = (const float*)d_in[13];
    const int*  a_src = (const int*)d_in[14];
    const int*  a_dst = (const int*)d_in[15];
    const int*  i_src = (const int*)d_in[16];
    const int*  i_dst = (const int*)d_in[17];
    float* out = (float*)d_out;
    const int e = in_sizes[14];

    float* xd    = (float*)sym(g_x);
    float* xp    = xd + (size_t)NN*FEAT;
    __half* h16d = (__half*)sym(g_h16);
    __half* h16p = h16d + (size_t)NN*FEAT;
    __half* m16  = (__half*)sym(g_m16);
    __half* m0   = m16;
    __half* m1   = m16 + 1*(size_t)NN*FEAT;
    __half* m2   = m16 + 2*(size_t)NN*FEAT;
    __half* m3   = m16 + 3*(size_t)NN*FEAT;
    __half* w16  = (__half*)sym(g_w16);
    auto W = [&](int slot) { return w16 + (size_t)slot * FF; };
    float* bsum0 = (float*)sym(g_bsum);
    float* bsum1 = bsum0 + FEAT;
    float* st    = (float*)sym(g_stats);
    float* st0d = st, *st0p = st + 2*FEAT, *st1d = st + 4*FEAT, *st1p = st + 6*FEAT;
    int*   cnt   = (int*)sym(g_cnt);

    cudaFuncSetAttribute(k_mma2, cudaFuncAttributeMaxDynamicSharedMemorySize, SMEM_BYTES);

    const bool ok = ctx.ok;
    cudaStream_t S0 = 0;
    cudaStream_t S1 = ok ? ctx.s1 : (cudaStream_t)0;
    auto rec  = [&](int i, cudaStream_t s) { if (ok) cudaEventRecord(ctx.ev[i], s); };
    auto wait = [&](cudaStream_t s, int i)  { if (ok) cudaStreamWaitEvent(s, ctx.ev[i], 0); };

    int xgrid = (NN*128 + 255)/256;
    int wgrid = (FF + 255)/256;
    dim3 ggrid(4, GY);

    auto gemm = [&](cudaStream_t s, const __half* A0, const __half* W0,
                    const float* bias, float* C, float* stats, int accum,
                    const __half* A1 = nullptr, const __half* W1 = nullptr,
                    const __half* A2 = nullptr, const __half* W2p = nullptr) {
        Segs t; t.n = 1;
        t.a[0] = A0; t.w[0] = W0;
        if (A1) { t.a[t.n] = A1; t.w[t.n] = W1; t.n++; }
        if (A2) { t.a[t.n] = A2; t.w[t.n] = W2p; t.n++; }
        k_mma2<<<ggrid, 256, SMEM_BYTES, s>>>(t, bias, C, stats, NN, accum);
    };

    // fork
    rec(E_START, S0);
    wait(S1, E_START);

    // ---- S0: stats zero (independent) + CSR build ----
    k_zero_float<<<(8*FEAT + 255)/256, 256, 0, S0>>>(st, 8*FEAT);
    k_zero_int<<<(4*NN + 255)/256, 256, 0, S0>>>(cnt, 4*NN);
    k_count<<<(e + 255)/256, 256, 0, S0>>>(a_src, a_dst, i_src, i_dst, e);
    k_scan<<<4, 1024, 0, S0>>>();
    k_fill<<<(e + 255)/256, 256, 0, S0>>>(a_src, a_dst, i_src, i_dst, e);

    // ---- S1: fp16 input conversions (single launch) ----
    {
        dim3 cg(xgrid, 2);
        k_toF16x2<<<cg, 256, 0, S1>>>(h16p, h_p, h16d, h_d, NN);
    }
    rec(E_X16, S1);

    // ---- S0: layer0 aggregates ----
    wait(S0, E_X16);
    k_aggregate<<<NN, 128, 0, S0>>>(m1, h16p, 1);
    rec(E_M1, S0);
    k_aggregate<<<NN, 128, 0, S0>>>(m0, h16d, 0);
    k_aggregate<<<NN, 128, 0, S0>>>(m2, h16p, 2);
    k_aggregate<<<NN, 128, 0, S0>>>(m3, h16p, 3);

    // ---- S1: weight conversions ----
    {
        dim3 cg2(wgrid, 2);
        k_combine2<<<cg2, 256, 0, S1>>>(W(2), Ws1, b1, bsum0, W(8), Ws2, b2, bsum1);
    }
    {
        WJobs jb;
        jb.src[0] = Ws1 + (size_t)FF;     jb.dst[0] = W(0);
        jb.src[1] = Wn1 + (size_t)FF;     jb.dst[1] = W(1);
        jb.src[2] = Wn1;                  jb.dst[2] = W(3);
        jb.src[3] = Wn1 + 2*(size_t)FF;   jb.dst[3] = W(4);
        jb.src[4] = Wn1 + 3*(size_t)FF;   jb.dst[4] = W(5);
        jb.src[5] = Ws2 + (size_t)FF;     jb.dst[5] = W(6);
        jb.src[6] = Wn2 + (size_t)FF;     jb.dst[6] = W(7);
        jb.src[7] = Wn2;                  jb.dst[7] = W(9);
        jb.src[8] = Wn2 + 2*(size_t)FF;   jb.dst[8] = W(10);
        jb.src[9] = Wn2 + 3*(size_t)FF;   jb.dst[9] = W(11);
        jb.src[10] = pWd;                 jb.dst[10] = W(12);
        jb.src[11] = pWp;                 jb.dst[11] = W(13);
        dim3 wg((FF/2 + 255)/256, 12);
        k_w12<<<wg, 256, 0, S1>>>(jb);
    }

    // ---- S1: layer0 self GEMMs ----
    gemm(S1, h16p, W(2), bsum0,     xp, nullptr, 0);         // protein self
    rec(E_PSELF, S1);
    gemm(S1, h16d, W(0), b1 + FEAT, xd, nullptr, 0);         // disease self

    // ---- S1: layer0 disease neigh + BN ----
    wait(S1, E_M1);
    gemm(S1, m1, W(1), nullptr, xd, st0d, 1);
    k_bnrelu<<<xgrid, 256, 0, S1>>>(xd, h16d, st0d, gam + 0*FEAT, bet + 0*FEAT, NN);
    rec(E_BND0, S1);

    // ---- S0: layer0 protein neigh + BN (aggs in-order on S0) ----
    wait(S0, E_PSELF);
    gemm(S0, m0, W(3), nullptr, xp, st0p, 1, m2, W(4), m3, W(5));
    k_bnrelu<<<xgrid, 256, 0, S0>>>(xp, h16p, st0p, gam + 1*FEAT, bet + 1*FEAT, NN);
    rec(E_BNP0, S0);

    // ---- layer1 aggregates ----
    wait(S0, E_BND0);
    k_aggregate<<<NN, 128, 0, S0>>>(m0, h16d, 0);
    rec(E_M0P, S0);
    k_aggregate<<<NN, 128, 0, S0>>>(m2, h16p, 2);
    k_aggregate<<<NN, 128, 0, S0>>>(m3, h16p, 3);

    wait(S1, E_BNP0);
    k_aggregate<<<NN, 128, 0, S1>>>(m1, h16p, 1);
    rec(E_M1P, S1);

    // ---- S1: layer1 disease chain + projection ----
    gemm(S1, h16d, W(6), b2 + FEAT, xd, nullptr, 0);
    gemm(S1, m1,   W(7), nullptr,   xd, st1d, 1);
    wait(S1, E_M0P);                  // h16d WAR: S0's m0' gather must finish before overwrite
    k_bnrelu<<<xgrid, 256, 0, S1>>>(xd, h16d, st1d, gam + 2*FEAT, bet + 2*FEAT, NN);
    gemm(S1, h16d, W(12), pbd, out, nullptr, 0);
    rec(E_S1, S1);

    // ---- S0: layer1 protein chain + projection ----
    gemm(S0, h16p, W(8), bsum1, xp, nullptr, 0);
    gemm(S0, m0,   W(9), nullptr, xp, st1p, 1, m2, W(10), m3, W(11));
    wait(S0, E_M1P);                  // h16p WAR: S1's m1' gather must finish before overwrite
    k_bnrelu<<<xgrid, 256, 0, S0>>>(xp, h16p, st1p, gam + 3*FEAT, bet + 3*FEAT, NN);
    gemm(S0, h16p, W(13), pbp, out + (size_t)NN*FEAT, nullptr, 0);

    // join
    wait(S0, E_S1);
}

// round 15
// speedup vs baseline: 1.5006x; 1.0018x over previous
#include <cuda_runtime.h>
#include <cuda_fp16.h>
#include <cstdint>
#include <cstddef>

#define NN 20000
#define FEAT 512
#define FF (FEAT*FEAT)
#define EE 320000
#define EPS 1e-5f
#define GY ((NN + 127) / 128)

// ---------------- scratch (device globals; no allocation allowed) ----------------
__device__ float  g_x[2][NN*FEAT];                 // fp32 GEMM outputs (BN input)
__device__ __half g_h16[2][(size_t)NN*FEAT];       // fp16 node feats (GEMM A + gather source)
__device__ __half g_m16[4][(size_t)NN*FEAT];       // fp16 aggregate means
__device__ __half g_w16[14][(size_t)FF];           // fp16 weights
__device__ float  g_bsum[2][FEAT];
__device__ float  g_stats[8*FEAT];
__device__ int    g_cnt[4][NN];
__device__ int    g_off[4][NN+1];
__device__ int    g_cur[4][NN];
__device__ int    g_srcid[4][EE];

// ---------------- small utils ----------------
__global__ void k_zero_int(int* p, int n) {
    int i = blockIdx.x*blockDim.x + threadIdx.x;
    if (i < n) p[i] = 0;
}
__global__ void k_zero_float(float* p, int n) {
    int i = blockIdx.x*blockDim.x + threadIdx.x;
    if (i < n) p[i] = 0.f;
}

// ---------------- CSR build ----------------
__global__ void k_count(const int* __restrict__ a_src, const int* __restrict__ a_dst,
                        const int* __restrict__ i_src, const int* __restrict__ i_dst, int e) {
    int idx = blockIdx.x*blockDim.x + threadIdx.x;
    if (idx >= e) return;
    atomicAdd(&g_cnt[0][a_dst[idx]], 1);
    atomicAdd(&g_cnt[1][a_src[idx]], 1);
    atomicAdd(&g_cnt[2][i_dst[idx]], 1);
    atomicAdd(&g_cnt[3][i_src[idx]], 1);
}

// one block per relation; warp-shuffle two-level scan (2 barriers total)
#define SCAN_PER 20   // ceil(20000/1024)
__global__ void k_scan() {
    int r = blockIdx.x;
    int t = threadIdx.x;                 // 0..1023
    int lane = t & 31, wid = t >> 5;
    int base = t * SCAN_PER;
    int loc[SCAN_PER];
    int sum = 0;
    #pragma unroll
    for (int i = 0; i < SCAN_PER; i++) {
        int idx = base + i;
        int c = (idx < NN) ? g_cnt[r][idx] : 0;
        loc[i] = sum;
        sum += c;
    }
    // inclusive warp scan of per-thread sums
    int v = sum;
    #pragma unroll
    for (int d = 1; d < 32; d <<= 1) {
        int u = __shfl_up_sync(0xFFFFFFFFu, v, d);
        if (lane >= d) v += u;
    }
    __shared__ int wsum[32];
    if (lane == 31) wsum[wid] = v;
    __syncthreads();
    if (wid == 0) {
        int w = wsum[lane];
        #pragma unroll
        for (int d = 1; d < 32; d <<= 1) {
            int u = __shfl_up_sync(0xFFFFFFFFu, w, d);
            if (lane >= d) w += u;
        }
        wsum[lane] = w;
    }
    __syncthreads();
    int warpoff = (wid == 0) ? 0 : wsum[wid - 1];
    int excl = warpoff + v - sum;        // exclusive offset for this thread's chunk
    #pragma unroll
    for (int i = 0; i < SCAN_PER; i++) {
        int idx = base + i;
        if (idx < NN) {
            int o = excl + loc[i];
            g_off[r][idx] = o;
            g_cur[r][idx] = o;
        }
    }
    if (t == 1023) g_off[r][NN] = excl + sum;
}

__global__ void k_fill(const int* __restrict__ a_src, const int* __restrict__ a_dst,
                       const int* __restrict__ i_src, const int* __restrict__ i_dst, int e) {
    int idx = blockIdx.x*blockDim.x + threadIdx.x;
    if (idx >= e) return;
    int p;
    p = atomicAdd(&g_cur[0][a_dst[idx]], 1); g_srcid[0][p] = a_src[idx];
    p = atomicAdd(&g_cur[1][a_src[idx]], 1); g_srcid[1][p] = a_dst[idx];
    p = atomicAdd(&g_cur[2][i_dst[idx]], 1); g_srcid[2][p] = i_src[idx];
    p = atomicAdd(&g_cur[3][i_src[idx]], 1); g_srcid[3][p] = i_dst[idx];
}

// ---------------- conversions ----------------
// grid.y = which tensor (0: p, 1: d)
__global__ void k_toF16x2(__half* __restrict__ d0, const float* __restrict__ s0,
                          __half* __restrict__ d1, const float* __restrict__ s1, int M) {
    __half* dst = blockIdx.y ? d1 : d0;
    const float* src = blockIdx.y ? s1 : s0;
    int i = blockIdx.x*blockDim.x + threadIdx.x;
    if (i >= M*128) return;
    int r = i >> 7, c = (i & 127) * 4;
    float4 v = *(const float4*)(src + (size_t)r*FEAT + c);
    __half2 p0 = __halves2half2(__float2half_rn(v.x), __float2half_rn(v.y));
    __half2 p1 = __halves2half2(__float2half_rn(v.z), __float2half_rn(v.w));
    *(__half2*)(dst + (size_t)r*FEAT + c)     = p0;
    *(__half2*)(dst + (size_t)r*FEAT + c + 2) = p1;
}

struct WJobs { const float* src[12]; __half* dst[12]; };
__global__ void k_w12(WJobs jobs) {
    int slot = blockIdx.y;
    int i = blockIdx.x*blockDim.x + threadIdx.x;
    if (i >= FF/2) return;
    const float2 v = *(const float2*)(jobs.src[slot] + 2*(size_t)i);
    __half2 h = __halves2half2(__float2half_rn(v.x), __float2half_rn(v.y));
    *(__half2*)(jobs.dst[slot] + 2*(size_t)i) = h;
}

// Wsum = Ws[0]+Ws[2]+Ws[3] (to fp16); bsum = b[0]+b[2]+b[3]
__global__ void k_combine16(__half* __restrict__ dst,
                            const float* __restrict__ Ws, const float* __restrict__ b,
                            float* __restrict__ bsum) {
    int i = blockIdx.x*blockDim.x + threadIdx.x;
    if (i < FF) {
        float x = Ws[i] + Ws[2*(size_t)FF + i] + Ws[3*(size_t)FF + i];
        dst[i] = __float2half_rn(x);
    }
    if (i < FEAT) bsum[i] = b[i] + b[2*FEAT + i] + b[3*FEAT + i];
}

// ---------------- aggregation (fp16 gather, fp32 accumulate, fp16 out) ----------------
__global__ void k_aggregate(__half* __restrict__ outh, const __half* __restrict__ hsrc, int rel) {
    int node = blockIdx.x;
    int t = threadIdx.x;  // 0..127
    int beg = g_off[rel][node];
    int end = g_off[rel][node+1];
    float ax = 0.f, ay = 0.f, az = 0.f, aw = 0.f;
    for (int j = beg; j < end; j++) {
        int s = g_srcid[rel][j];
        uint2 v = __ldg((const uint2*)(hsrc + (size_t)s*FEAT) + t);
        __half2 h0 = *(__half2*)&v.x;
        __half2 h1 = *(__half2*)&v.y;
        float2 f0 = __half22float2(h0);
        float2 f1 = __half22float2(h1);
        ax += f0.x; ay += f0.y; az += f1.x; aw += f1.y;
    }
    float inv = (end > beg) ? 1.f / (float)(end - beg) : 0.f;
    __half2 p0 = __halves2half2(__float2half_rn(ax*inv), __float2half_rn(ay*inv));
    __half2 p1 = __halves2half2(__float2half_rn(az*inv), __float2half_rn(aw*inv));
    size_t base = (size_t)node*FEAT + t*4;
    *(__half2*)(outh + base)     = p0;
    *(__half2*)(outh + base + 2) = p1;
}

// ---------------- fp16 tensor-core GEMM (multi-segment, 3-stage pipeline) ----------------
struct Segs {
    const __half* a[4];
    const __half* w[4];
    int n;
};

__device__ __forceinline__ uint32_t sptr(const void* p) {
    return (uint32_t)__cvta_generic_to_shared(p);
}
__device__ __forceinline__ void cpa16(uint32_t sa, const void* g, bool pred) {
    int sz = pred ? 16 : 0;
    asm volatile("cp.async.cg.shared.global [%0], [%1], 16, %2;\n" :: "r"(sa), "l"(g), "r"(sz));
}

#define APAD 40
#define BPAD 136
#define A_ELEMS (128*APAD)
#define B_ELEMS (32*BPAD)
#define STG_ELEMS (A_ELEMS + B_ELEMS)
#define OFF_A(buf) ((buf)*STG_ELEMS)
#define OFF_B(buf) ((buf)*STG_ELEMS + A_ELEMS)
#define SMEM_ELEMS (3*STG_ELEMS)
#define SMEM_BYTES (SMEM_ELEMS*2)

__global__ __launch_bounds__(256)
void k_mma2(const Segs segs, const float* __restrict__ bias, float* __restrict__ C,
            float* __restrict__ stats, int M, int accum)
{
    extern __shared__ __align__(16) __half sm[];

    const int tid  = threadIdx.x;
    const int lane = tid & 31;
    const int warp = tid >> 5;
    const int wm = (warp & 1) * 64;      // 2 warps along M
    const int wn = (warp >> 1) * 32;     // 4 warps along N
    const int row0 = blockIdx.y * 128;
    const int col0 = blockIdx.x * 128;

    float acc[4][4][4];
    #pragma unroll
    for (int i = 0; i < 4; i++)
        #pragma unroll
        for (int j = 0; j < 4; j++)
            #pragma unroll
            for (int k = 0; k < 4; k++) acc[i][j][k] = 0.f;

    const int T = segs.n * 16;

    auto issue = [&](int t) {
        int buf = t % 3;
        int s  = t >> 4;
        int k0 = (t & 15) * 32;
        const __half* A = segs.a[s];
        const __half* W = segs.w[s];
        #pragma unroll
        for (int l = 0; l < 2; l++) {
            int idx = tid + l*256;       // 0..511
            int r  = idx >> 2;           // 0..127
            int c  = (idx & 3) * 8;      // 0,8,16,24
            int gr = row0 + r;
            cpa16(sptr(sm + OFF_A(buf) + r*APAD + c), A + (size_t)gr*FEAT + k0 + c, gr < M);
            int br = idx >> 4;           // 0..31
            int bc = (idx & 15) * 8;     // 0..120
            cpa16(sptr(sm + OFF_B(buf) + br*BPAD + bc), W + (size_t)(k0 + br)*512 + col0 + bc, true);
        }
        asm volatile("cp.async.commit_group;\n" ::: "memory");
    };

    issue(0);
    if (T > 1) issue(1);

    const int g2 = lane >> 3, lr = lane & 7;

    for (int t = 0; t < T; t++) {
        int buf = t % 3;
        if (t + 1 < T) asm volatile("cp.async.wait_group 1;\n" ::: "memory");
        else           asm volatile("cp.async.wait_group 0;\n" ::: "memory");
        __syncthreads();
        if (t + 2 < T) issue(t + 2);

        #pragma unroll
        for (int ks = 0; ks < 2; ks++) {
            int arow = wm + (g2 & 1)*8 + lr;
            int acol = ks*16 + (g2 >> 1)*8;
            uint32_t af[4][4];
            #pragma unroll
            for (int mi = 0; mi < 4; mi++) {
                uint32_t ad = sptr(sm + OFF_A(buf) + (arow + mi*16)*APAD + acol);
                asm volatile("ldmatrix.sync.aligned.m8n8.x4.shared.b16 {%0,%1,%2,%3}, [%4];\n"
                    : "=r"(af[mi][0]), "=r"(af[mi][1]), "=r"(af[mi][2]), "=r"(af[mi][3])
                    : "r"(ad));
            }
            int brow = ks*16 + (g2 & 1)*8 + lr;
            uint32_t bf[2][4];
            #pragma unroll
            for (int nj = 0; nj < 2; nj++) {
                int bcol = wn + nj*16 + (g2 >> 1)*8;
                uint32_t bd = sptr(sm + OFF_B(buf) + brow*BPAD + bcol);
                asm volatile("ldmatrix.sync.aligned.m8n8.x4.trans.shared.b16 {%0,%1,%2,%3}, [%4];\n"
                    : "=r"(bf[nj][0]), "=r"(bf[nj][1]), "=r"(bf[nj][2]), "=r"(bf[nj][3])
                    : "r"(bd));
            }
            #pragma unroll
            for (int mi = 0; mi < 4; mi++)
                #pragma unroll
                for (int ni = 0; ni < 4; ni++) {
                    uint32_t b0 = bf[ni >> 1][(ni & 1)*2];
                    uint32_t b1 = bf[ni >> 1][(ni & 1)*2 + 1];
                    asm volatile(
                        "mma.sync.aligned.m16n8k16.row.col.f32.f16.f16.f32 "
                        "{%0,%1,%2,%3}, {%4,%5,%6,%7}, {%8,%9}, {%0,%1,%2,%3};\n"
                        : "+f"(acc[mi][ni][0]), "+f"(acc[mi][ni][1]),
                          "+f"(acc[mi][ni][2]), "+f"(acc[mi][ni][3])
                        : "r"(af[mi][0]), "r"(af[mi][1]), "r"(af[mi][2]), "r"(af[mi][3]),
                          "r"(b0), "r"(b1));
                }
        }
    }

    // epilogue: (accumulate|bias) + store + optional fused column stats
    float vsum[4][2], vsq[4][2];
    #pragma unroll
    for (int ni = 0; ni < 4; ni++) { vsum[ni][0]=vsum[ni][1]=vsq[ni][0]=vsq[ni][1]=0.f; }

    #pragma unroll
    for (int mi = 0; mi < 4; mi++) {
        int gr0 = row0 + wm + mi*16 + (lane >> 2);
        int gr1 = gr0 + 8;
        bool p0 = gr0 < M, p1 = gr1 < M;
        #pragma unroll
        for (int ni = 0; ni < 4; ni++) {
            int gc = col0 + wn + ni*8 + (lane & 3)*2;
            float a00 = acc[mi][ni][0], a01 = acc[mi][ni][1];
            float a10 = acc[mi][ni][2], a11 = acc[mi][ni][3];
            if (accum) {
                if (p0) {
                    float2 c0 = *(float2*)(C + (size_t)gr0*FEAT + gc);
                    a00 += c0.x; a01 += c0.y;
                }
                if (p1) {
                    float2 c1 = *(float2*)(C + (size_t)gr1*FEAT + gc);
                    a10 += c1.x; a11 += c1.y;
                }
            } else {
                float b0 = bias[gc], b1 = bias[gc+1];
                a00 += b0; a01 += b1; a10 += b0; a11 += b1;
            }
            if (p0) {
                float2 o; o.x = a00; o.y = a01;
                *(float2*)(C + (size_t)gr0*FEAT + gc) = o;
                vsum[ni][0] += a00; vsq[ni][0] += a00*a00;
                vsum[ni][1] += a01; vsq[ni][1] += a01*a01;
            }
            if (p1) {
                float2 o; o.x = a10; o.y = a11;
                *(float2*)(C + (size_t)gr1*FEAT + gc) = o;
                vsum[ni][0] += a10; vsq[ni][0] += a10*a10;
                vsum[ni][1] += a11; vsq[ni][1] += a11*a11;
            }
        }
    }

    if (stats) {
        #pragma unroll
        for (int ni = 0; ni < 4; ni++) {
            #pragma unroll
            for (int j = 0; j < 2; j++) {
                float s = vsum[ni][j], q = vsq[ni][j];
                #pragma unroll
                for (int st = 4; st < 32; st <<= 1) {
                    s += __shfl_xor_sync(0xFFFFFFFFu, s, st);
                    q += __shfl_xor_sync(0xFFFFFFFFu, q, st);
                }
                if (lane < 4) {
                    int c = col0 + wn + ni*8 + lane*2 + j;
                    atomicAdd(&stats[c], s);
                    atomicAdd(&stats[FEAT + c], q);
                }
            }
        }
    }
}

// ---------------- BatchNorm (apply): fp32 in -> fp16 out ----------------
__global__ void k_bnrelu(const float* __restrict__ X, __half* __restrict__ X16,
                         const float* __restrict__ stats,
                         const float* __restrict__ gamma, const float* __restrict__ beta, int M) {
    int i = blockIdx.x*blockDim.x + threadIdx.x;
    if (i >= M*128) return;
    int r = i >> 7, c = (i & 127) * 4;
    float invM = 1.f / (float)M;
    float4 x = *(const float4*)(X + (size_t)r*FEAT + c);
    float xv[4] = {x.x, x.y, x.z, x.w};
    float y[4];
    #pragma unroll
    for (int j = 0; j < 4; j++) {
        int cc = c + j;
        float mean = stats[cc] * invM;
        float var  = stats[FEAT + cc] * invM - mean*mean;
        float v = gamma[cc] * (xv[j] - mean) * rsqrtf(var + EPS) + beta[cc];
        y[j] = v > 0.f ? v : 0.f;
    }
    __half2 p0 = __halves2half2(__float2half_rn(y[0]), __float2half_rn(y[1]));
    __half2 p1 = __halves2half2(__float2half_rn(y[2]), __float2half_rn(y[3]));
    *(__half2*)(X16 + (size_t)r*FEAT + c)     = p0;
    *(__half2*)(X16 + (size_t)r*FEAT + c + 2) = p1;
}

// ---------------- host ----------------
static void* sym(const void* s) { void* p = nullptr; cudaGetSymbolAddress(&p, s); return p; }

struct StreamCtx {
    cudaStream_t s1;
    cudaEvent_t ev[10];
    bool ok;
    StreamCtx() {
        ok = (cudaStreamCreateWithFlags(&s1, cudaStreamNonBlocking) == cudaSuccess);
        for (int i = 0; i < 10; i++)
            if (cudaEventCreateWithFlags(&ev[i], cudaEventDisableTiming) != cudaSuccess) ok = false;
    }
};

enum { E_START=0, E_X16, E_M1, E_PSELF, E_BND0, E_BNP0, E_M0P, E_M1P, E_S1 };

extern "C" void kernel_launch(void* const* d_in, const int* in_sizes, int n_in,
                              void* d_out, int out_size)
{
    static StreamCtx ctx;

    const float* h_d  = (const float*)d_in[0];
    const float* h_p  = (const float*)d_in[1];
    const float* Ws1  = (const float*)d_in[2];
    const float* Wn1  = (const float*)d_in[3];
    const float* b1   = (const float*)d_in[4];
    const float* Ws2  = (const float*)d_in[5];
    const float* Wn2  = (const float*)d_in[6];
    const float* b2   = (const float*)d_in[7];
    const float* gam  = (const float*)d_in[8];
    const float* bet  = (const float*)d_in[9];
    const float* pWd  = (const float*)d_in[10];
    const float* pbd  = (const float*)d_in[11];
    const float* pWp  = (const float*)d_in[12];
    const float* pbp  = (const float*)d_in[13];
    const int*  a_src = (const int*)d_in[14];
    const int*  a_dst = (const int*)d_in[15];
    const int*  i_src = (const int*)d_in[16];
    const int*  i_dst = (const int*)d_in[17];
    float* out = (float*)d_out;
    const int e = in_sizes[14];

    float* xd    = (float*)sym(g_x);
    float* xp    = xd + (size_t)NN*FEAT;
    __half* h16d = (__half*)sym(g_h16);
    __half* h16p = h16d + (size_t)NN*FEAT;
    __half* m16  = (__half*)sym(g_m16);
    __half* m0   = m16;
    __half* m1   = m16 + 1*(size_t)NN*FEAT;
    __half* m2   = m16 + 2*(size_t)NN*FEAT;
    __half* m3   = m16 + 3*(size_t)NN*FEAT;
    __half* w16  = (__half*)sym(g_w16);
    auto W = [&](int slot) { return w16 + (size_t)slot * FF; };
    float* bsum0 = (float*)sym(g_bsum);
    float* bsum1 = bsum0 + FEAT;
    float* st    = (float*)sym(g_stats);
    float* st0d = st, *st0p = st + 2*FEAT, *st1d = st + 4*FEAT, *st1p = st + 6*FEAT;
    int*   cnt   = (int*)sym(g_cnt);

    cudaFuncSetAttribute(k_mma2, cudaFuncAttributeMaxDynamicSharedMemorySize, SMEM_BYTES);

    const bool ok = ctx.ok;
    cudaStream_t S0 = 0;
    cudaStream_t S1 = ok ? ctx.s1 : (cudaStream_t)0;
    auto rec  = [&](int i, cudaStream_t s) { if (ok) cudaEventRecord(ctx.ev[i], s); };
    auto wait = [&](cudaStream_t s, int i)  { if (ok) cudaStreamWaitEvent(s, ctx.ev[i], 0); };

    int xgrid = (NN*128 + 255)/256;
    int wgrid = (FF + 255)/256;
    dim3 ggrid(4, GY);

    auto gemm = [&](cudaStream_t s, const __half* A0, const __half* W0,
                    const float* bias, float* C, float* stats, int accum,
                    const __half* A1 = nullptr, const __half* W1 = nullptr,
                    const __half* A2 = nullptr, const __half* W2p = nullptr) {
        Segs t; t.n = 1;
        t.a[0] = A0; t.w[0] = W0;
        if (A1) { t.a[t.n] = A1; t.w[t.n] = W1; t.n++; }
        if (A2) { t.a[t.n] = A2; t.w[t.n] = W2p; t.n++; }
        k_mma2<<<ggrid, 256, SMEM_BYTES, s>>>(t, bias, C, stats, NN, accum);
    };

    // fork
    rec(E_START, S0);
    wait(S1, E_START);

    // ---- S0: CSR build ----
    k_zero_int<<<(4*NN + 255)/256, 256, 0, S0>>>(cnt, 4*NN);
    k_count<<<(e + 255)/256, 256, 0, S0>>>(a_src, a_dst, i_src, i_dst, e);
    k_scan<<<4, 1024, 0, S0>>>();
    k_fill<<<(e + 255)/256, 256, 0, S0>>>(a_src, a_dst, i_src, i_dst, e);

    // ---- S1: fp16 input conversions (single launch) ----
    {
        dim3 cg(xgrid, 2);
        k_toF16x2<<<cg, 256, 0, S1>>>(h16p, h_p, h16d, h_d, NN);
    }
    rec(E_X16, S1);

    // ---- S0: layer0 aggregates ----
    wait(S0, E_X16);
    k_aggregate<<<NN, 128, 0, S0>>>(m1, h16p, 1);
    rec(E_M1, S0);
    k_aggregate<<<NN, 128, 0, S0>>>(m0, h16d, 0);
    k_aggregate<<<NN, 128, 0, S0>>>(m2, h16p, 2);
    k_aggregate<<<NN, 128, 0, S0>>>(m3, h16p, 3);

    // ---- S1: weight conversions + stats zero ----
    k_combine16<<<wgrid, 256, 0, S1>>>(W(2), Ws1, b1, bsum0);
    k_combine16<<<wgrid, 256, 0, S1>>>(W(8), Ws2, b2, bsum1);
    {
        WJobs jb;
        jb.src[0] = Ws1 + (size_t)FF;     jb.dst[0] = W(0);
        jb.src[1] = Wn1 + (size_t)FF;     jb.dst[1] = W(1);
        jb.src[2] = Wn1;                  jb.dst[2] = W(3);
        jb.src[3] = Wn1 + 2*(size_t)FF;   jb.dst[3] = W(4);
        jb.src[4] = Wn1 + 3*(size_t)FF;   jb.dst[4] = W(5);
        jb.src[5] = Ws2 + (size_t)FF;     jb.dst[5] = W(6);
        jb.src[6] = Wn2 + (size_t)FF;     jb.dst[6] = W(7);
        jb.src[7] = Wn2;                  jb.dst[7] = W(9);
        jb.src[8] = Wn2 + 2*(size_t)FF;   jb.dst[8] = W(10);
        jb.src[9] = Wn2 + 3*(size_t)FF;   jb.dst[9] = W(11);
        jb.src[10] = pWd;                 jb.dst[10] = W(12);
        jb.src[11] = pWp;                 jb.dst[11] = W(13);
        dim3 wg((FF/2 + 255)/256, 12);
        k_w12<<<wg, 256, 0, S1>>>(jb);
    }
    k_zero_float<<<(8*FEAT + 255)/256, 256, 0, S1>>>(st, 8*FEAT);

    // ---- S1: layer0 self GEMMs ----
    gemm(S1, h16p, W(2), bsum0,     xp, nullptr, 0);         // protein self
    rec(E_PSELF, S1);
    gemm(S1, h16d, W(0), b1 + FEAT, xd, nullptr, 0);         // disease self

    // ---- S1: layer0 disease neigh + BN ----
    wait(S1, E_M1);
    gemm(S1, m1, W(1), nullptr, xd, st0d, 1);
    k_bnrelu<<<xgrid, 256, 0, S1>>>(xd, h16d, st0d, gam + 0*FEAT, bet + 0*FEAT, NN);
    rec(E_BND0, S1);

    // ---- S0: layer0 protein neigh + BN (aggs in-order on S0) ----
    wait(S0, E_PSELF);
    gemm(S0, m0, W(3), nullptr, xp, st0p, 1, m2, W(4), m3, W(5));
    k_bnrelu<<<xgrid, 256, 0, S0>>>(xp, h16p, st0p, gam + 1*FEAT, bet + 1*FEAT, NN);
    rec(E_BNP0, S0);

    // ---- layer1 aggregates ----
    wait(S0, E_BND0);
    k_aggregate<<<NN, 128, 0, S0>>>(m0, h16d, 0);
    rec(E_M0P, S0);
    k_aggregate<<<NN, 128, 0, S0>>>(m2, h16p, 2);
    k_aggregate<<<NN, 128, 0, S0>>>(m3, h16p, 3);

    wait(S1, E_BNP0);
    k_aggregate<<<NN, 128, 0, S1>>>(m1, h16p, 1);
    rec(E_M1P, S1);

    // ---- S1: layer1 disease chain + projection ----
    gemm(S1, h16d, W(6), b2 + FEAT, xd, nullptr, 0);
    gemm(S1, m1,   W(7), nullptr,   xd, st1d, 1);
    wait(S1, E_M0P);                  // h16d WAR: S0's m0' gather must finish before overwrite
    k_bnrelu<<<xgrid, 256, 0, S1>>>(xd, h16d, st1d, gam + 2*FEAT, bet + 2*FEAT, NN);
    gemm(S1, h16d, W(12), pbd, out, nullptr, 0);
    rec(E_S1, S1);

    // ---- S0: layer1 protein chain + projection ----
    gemm(S0, h16p, W(8), bsum1, xp, nullptr, 0);
    gemm(S0, m0,   W(9), nullptr, xp, st1p, 1, m2, W(10), m3, W(11));
    wait(S0, E_M1P);                  // h16p WAR: S1's m1' gather must finish before overwrite
    k_bnrelu<<<xgrid, 256, 0, S0>>>(xp, h16p, st1p, gam + 3*FEAT, bet + 3*FEAT, NN);
    gemm(S0, h16p, W(13), pbp, out + (size_t)NN*FEAT, nullptr, 0);

    // join
    wait(S0, E_S1);
}

// round 16
// speedup vs baseline: 1.5185x; 1.0119x over previous
#include <cuda_runtime.h>
#include <cuda_fp16.h>
#include <cstdint>
#include <cstddef>

#define NN 20000
#define FEAT 512
#define FF (FEAT*FEAT)
#define EE 320000
#define EPS 1e-5f
#define GY ((NN + 127) / 128)

// ---------------- scratch (device globals; no allocation allowed) ----------------
__device__ float  g_x[2][NN*FEAT];                 // fp32 GEMM outputs (BN input)
__device__ __half g_h16[2][(size_t)NN*FEAT];       // fp16 node feats (GEMM A + gather source)
__device__ __half g_m16[4][(size_t)NN*FEAT];       // fp16 aggregate means
__device__ __half g_w16[14][(size_t)FF];           // fp16 weights
__device__ float  g_bsum[2][FEAT];
__device__ float  g_stats[8*FEAT];
__device__ int    g_cnt[4][NN];
__device__ int    g_off[4][NN+1];
__device__ int    g_cur[4][NN];
__device__ int    g_srcid[4][EE];

// ---------------- small utils ----------------
__global__ void k_zero_int(int* p, int n) {
    int i = blockIdx.x*blockDim.x + threadIdx.x;
    if (i < n) p[i] = 0;
}
__global__ void k_zero_float(float* p, int n) {
    int i = blockIdx.x*blockDim.x + threadIdx.x;
    if (i < n) p[i] = 0.f;
}

// ---------------- CSR build ----------------
__global__ void k_count(const int* __restrict__ a_src, const int* __restrict__ a_dst,
                        const int* __restrict__ i_src, const int* __restrict__ i_dst, int e) {
    int idx = blockIdx.x*blockDim.x + threadIdx.x;
    if (idx >= e) return;
    atomicAdd(&g_cnt[0][a_dst[idx]], 1);
    atomicAdd(&g_cnt[1][a_src[idx]], 1);
    atomicAdd(&g_cnt[2][i_dst[idx]], 1);
    atomicAdd(&g_cnt[3][i_src[idx]], 1);
}

// one block per relation; warp-shuffle two-level scan (2 barriers total)
#define SCAN_PER 20   // ceil(20000/1024)
__global__ void k_scan() {
    int r = blockIdx.x;
    int t = threadIdx.x;                 // 0..1023
    int lane = t & 31, wid = t >> 5;
    int base = t * SCAN_PER;
    int loc[SCAN_PER];
    int sum = 0;
    #pragma unroll
    for (int i = 0; i < SCAN_PER; i++) {
        int idx = base + i;
        int c = (idx < NN) ? g_cnt[r][idx] : 0;
        loc[i] = sum;
        sum += c;
    }
    int v = sum;
    #pragma unroll
    for (int d = 1; d < 32; d <<= 1) {
        int u = __shfl_up_sync(0xFFFFFFFFu, v, d);
        if (lane >= d) v += u;
    }
    __shared__ int wsum[32];
    if (lane == 31) wsum[wid] = v;
    __syncthreads();
    if (wid == 0) {
        int w = wsum[lane];
        #pragma unroll
        for (int d = 1; d < 32; d <<= 1) {
            int u = __shfl_up_sync(0xFFFFFFFFu, w, d);
            if (lane >= d) w += u;
        }
        wsum[lane] = w;
    }
    __syncthreads();
    int warpoff = (wid == 0) ? 0 : wsum[wid - 1];
    int excl = warpoff + v - sum;
    #pragma unroll
    for (int i = 0; i < SCAN_PER; i++) {
        int idx = base + i;
        if (idx < NN) {
            int o = excl + loc[i];
            g_off[r][idx] = o;
            g_cur[r][idx] = o;
        }
    }
    if (t == 1023) g_off[r][NN] = excl + sum;
}

__global__ void k_fill(const int* __restrict__ a_src, const int* __restrict__ a_dst,
                       const int* __restrict__ i_src, const int* __restrict__ i_dst, int e) {
    int idx = blockIdx.x*blockDim.x + threadIdx.x;
    if (idx >= e) return;
    int p;
    p = atomicAdd(&g_cur[0][a_dst[idx]], 1); g_srcid[0][p] = a_src[idx];
    p = atomicAdd(&g_cur[1][a_src[idx]], 1); g_srcid[1][p] = a_dst[idx];
    p = atomicAdd(&g_cur[2][i_dst[idx]], 1); g_srcid[2][p] = i_src[idx];
    p = atomicAdd(&g_cur[3][i_src[idx]], 1); g_srcid[3][p] = i_dst[idx];
}

// ---------------- conversions ----------------
// grid.y = which tensor (0: p, 1: d)
__global__ void k_toF16x2(__half* __restrict__ d0, const float* __restrict__ s0,
                          __half* __restrict__ d1, const float* __restrict__ s1, int M) {
    __half* dst = blockIdx.y ? d1 : d0;
    const float* src = blockIdx.y ? s1 : s0;
    int i = blockIdx.x*blockDim.x + threadIdx.x;
    if (i >= M*128) return;
    int r = i >> 7, c = (i & 127) * 4;
    float4 v = *(const float4*)(src + (size_t)r*FEAT + c);
    __half2 p0 = __halves2half2(__float2half_rn(v.x), __float2half_rn(v.y));
    __half2 p1 = __halves2half2(__float2half_rn(v.z), __float2half_rn(v.w));
    *(__half2*)(dst + (size_t)r*FEAT + c)     = p0;
    *(__half2*)(dst + (size_t)r*FEAT + c + 2) = p1;
}

struct WJobs { const float* src[12]; __half* dst[12]; };
__global__ void k_w12(WJobs jobs) {
    int slot = blockIdx.y;
    int i = blockIdx.x*blockDim.x + threadIdx.x;
    if (i >= FF/2) return;
    const float2 v = *(const float2*)(jobs.src[slot] + 2*(size_t)i);
    __half2 h = __halves2half2(__float2half_rn(v.x), __float2half_rn(v.y));
    *(__half2*)(jobs.dst[slot] + 2*(size_t)i) = h;
}

// Wsum = Ws[0]+Ws[2]+Ws[3] (to fp16); bsum = b[0]+b[2]+b[3]
__global__ void k_combine16(__half* __restrict__ dst,
                            const float* __restrict__ Ws, const float* __restrict__ b,
                            float* __restrict__ bsum) {
    int i = blockIdx.x*blockDim.x + threadIdx.x;
    if (i < FF) {
        float x = Ws[i] + Ws[2*(size_t)FF + i] + Ws[3*(size_t)FF + i];
        dst[i] = __float2half_rn(x);
    }
    if (i < FEAT) bsum[i] = b[i] + b[2*FEAT + i] + b[3*FEAT + i];
}

// ---------------- aggregation (fp16 gather, fp32 accumulate, fp16 out) ----------------
__global__ void k_aggregate(__half* __restrict__ outh, const __half* __restrict__ hsrc, int rel) {
    int node = blockIdx.x;
    int t = threadIdx.x;  // 0..127
    int beg = g_off[rel][node];
    int end = g_off[rel][node+1];
    float ax = 0.f, ay = 0.f, az = 0.f, aw = 0.f;
    for (int j = beg; j < end; j++) {
        int s = g_srcid[rel][j];
        uint2 v = __ldg((const uint2*)(hsrc + (size_t)s*FEAT) + t);
        __half2 h0 = *(__half2*)&v.x;
        __half2 h1 = *(__half2*)&v.y;
        float2 f0 = __half22float2(h0);
        float2 f1 = __half22float2(h1);
        ax += f0.x; ay += f0.y; az += f1.x; aw += f1.y;
    }
    float inv = (end > beg) ? 1.f / (float)(end - beg) : 0.f;
    __half2 p0 = __halves2half2(__float2half_rn(ax*inv), __float2half_rn(ay*inv));
    __half2 p1 = __halves2half2(__float2half_rn(az*inv), __float2half_rn(aw*inv));
    size_t base = (size_t)node*FEAT + t*4;
    *(__half2*)(outh + base)     = p0;
    *(__half2*)(outh + base + 2) = p1;
}

// ---------------- fp16 tensor-core GEMM (multi-segment, 3-stage pipeline) ----------------
struct Segs {
    const __half* a[4];
    const __half* w[4];
    int n;
};

__device__ __forceinline__ uint32_t sptr(const void* p) {
    return (uint32_t)__cvta_generic_to_shared(p);
}
__device__ __forceinline__ void cpa16(uint32_t sa, const void* g, bool pred) {
    int sz = pred ? 16 : 0;
    asm volatile("cp.async.cg.shared.global [%0], [%1], 16, %2;\n" :: "r"(sa), "l"(g), "r"(sz));
}

#define APAD 40
#define BPAD 136
#define A_ELEMS (128*APAD)
#define B_ELEMS (32*BPAD)
#define STG_ELEMS (A_ELEMS + B_ELEMS)
#define OFF_A(buf) ((buf)*STG_ELEMS)
#define OFF_B(buf) ((buf)*STG_ELEMS + A_ELEMS)
#define SMEM_ELEMS (3*STG_ELEMS)
#define SMEM_BYTES (SMEM_ELEMS*2)

__global__ __launch_bounds__(256)
void k_mma2(const Segs segs, const float* __restrict__ bias, float* __restrict__ C,
            float* __restrict__ stats, int M, int accum)
{
    extern __shared__ __align__(16) __half sm[];

    const int tid  = threadIdx.x;
    const int lane = tid & 31;
    const int warp = tid >> 5;
    const int wm = (warp & 1) * 64;      // 2 warps along M
    const int wn = (warp >> 1) * 32;     // 4 warps along N
    const int row0 = blockIdx.y * 128;
    const int col0 = blockIdx.x * 128;

    float acc[4][4][4];
    #pragma unroll
    for (int i = 0; i < 4; i++)
        #pragma unroll
        for (int j = 0; j < 4; j++)
            #pragma unroll
            for (int k = 0; k < 4; k++) acc[i][j][k] = 0.f;

    const int T = segs.n * 16;

    auto issue = [&](int t) {
        int buf = t % 3;
        int s  = t >> 4;
        int k0 = (t & 15) * 32;
        const __half* A = segs.a[s];
        const __half* W = segs.w[s];
        #pragma unroll
        for (int l = 0; l < 2; l++) {
            int idx = tid + l*256;       // 0..511
            int r  = idx >> 2;           // 0..127
            int c  = (idx & 3) * 8;      // 0,8,16,24
            int gr = row0 + r;
            cpa16(sptr(sm + OFF_A(buf) + r*APAD + c), A + (size_t)gr*FEAT + k0 + c, gr < M);
            int br = idx >> 4;           // 0..31
            int bc = (idx & 15) * 8;     // 0..120
            cpa16(sptr(sm + OFF_B(buf) + br*BPAD + bc), W + (size_t)(k0 + br)*512 + col0 + bc, true);
        }
        asm volatile("cp.async.commit_group;\n" ::: "memory");
    };

    issue(0);
    if (T > 1) issue(1);

    const int g2 = lane >> 3, lr = lane & 7;

    for (int t = 0; t < T; t++) {
        int buf = t % 3;
        if (t + 1 < T) asm volatile("cp.async.wait_group 1;\n" ::: "memory");
        else           asm volatile("cp.async.wait_group 0;\n" ::: "memory");
        __syncthreads();
        if (t + 2 < T) issue(t + 2);

        #pragma unroll
        for (int ks = 0; ks < 2; ks++) {
            int arow = wm + (g2 & 1)*8 + lr;
            int acol = ks*16 + (g2 >> 1)*8;
            uint32_t af[4][4];
            #pragma unroll
            for (int mi = 0; mi < 4; mi++) {
                uint32_t ad = sptr(sm + OFF_A(buf) + (arow + mi*16)*APAD + acol);
                asm volatile("ldmatrix.sync.aligned.m8n8.x4.shared.b16 {%0,%1,%2,%3}, [%4];\n"
                    : "=r"(af[mi][0]), "=r"(af[mi][1]), "=r"(af[mi][2]), "=r"(af[mi][3])
                    : "r"(ad));
            }
            int brow = ks*16 + (g2 & 1)*8 + lr;
            uint32_t bf[2][4];
            #pragma unroll
            for (int nj = 0; nj < 2; nj++) {
                int bcol = wn + nj*16 + (g2 >> 1)*8;
                uint32_t bd = sptr(sm + OFF_B(buf) + brow*BPAD + bcol);
                asm volatile("ldmatrix.sync.aligned.m8n8.x4.trans.shared.b16 {%0,%1,%2,%3}, [%4];\n"
                    : "=r"(bf[nj][0]), "=r"(bf[nj][1]), "=r"(bf[nj][2]), "=r"(bf[nj][3])
                    : "r"(bd));
            }
            #pragma unroll
            for (int mi = 0; mi < 4; mi++)
                #pragma unroll
                for (int ni = 0; ni < 4; ni++) {
                    uint32_t b0 = bf[ni >> 1][(ni & 1)*2];
                    uint32_t b1 = bf[ni >> 1][(ni & 1)*2 + 1];
                    asm volatile(
                        "mma.sync.aligned.m16n8k16.row.col.f32.f16.f16.f32 "
                        "{%0,%1,%2,%3}, {%4,%5,%6,%7}, {%8,%9}, {%0,%1,%2,%3};\n"
                        : "+f"(acc[mi][ni][0]), "+f"(acc[mi][ni][1]),
                          "+f"(acc[mi][ni][2]), "+f"(acc[mi][ni][3])
                        : "r"(af[mi][0]), "r"(af[mi][1]), "r"(af[mi][2]), "r"(af[mi][3]),
                          "r"(b0), "r"(b1));
                }
        }
    }

    // epilogue: (accumulate|bias) + store + optional fused column stats
    float vsum[4][2], vsq[4][2];
    #pragma unroll
    for (int ni = 0; ni < 4; ni++) { vsum[ni][0]=vsum[ni][1]=vsq[ni][0]=vsq[ni][1]=0.f; }

    #pragma unroll
    for (int mi = 0; mi < 4; mi++) {
        int gr0 = row0 + wm + mi*16 + (lane >> 2);
        int gr1 = gr0 + 8;
        bool p0 = gr0 < M, p1 = gr1 < M;
        #pragma unroll
        for (int ni = 0; ni < 4; ni++) {
            int gc = col0 + wn + ni*8 + (lane & 3)*2;
            float a00 = acc[mi][ni][0], a01 = acc[mi][ni][1];
            float a10 = acc[mi][ni][2], a11 = acc[mi][ni][3];
            if (accum) {
                if (p0) {
                    float2 c0 = *(float2*)(C + (size_t)gr0*FEAT + gc);
                    a00 += c0.x; a01 += c0.y;
                }
                if (p1) {
                    float2 c1 = *(float2*)(C + (size_t)gr1*FEAT + gc);
                    a10 += c1.x; a11 += c1.y;
                }
            } else {
                float b0 = bias[gc], b1 = bias[gc+1];
                a00 += b0; a01 += b1; a10 += b0; a11 += b1;
            }
            if (p0) {
                float2 o; o.x = a00; o.y = a01;
                *(float2*)(C + (size_t)gr0*FEAT + gc) = o;
                vsum[ni][0] += a00; vsq[ni][0] += a00*a00;
                vsum[ni][1] += a01; vsq[ni][1] += a01*a01;
            }
            if (p1) {
                float2 o; o.x = a10; o.y = a11;
                *(float2*)(C + (size_t)gr1*FEAT + gc) = o;
                vsum[ni][0] += a10; vsq[ni][0] += a10*a10;
                vsum[ni][1] += a11; vsq[ni][1] += a11*a11;
            }
        }
    }

    if (stats) {
        #pragma unroll
        for (int ni = 0; ni < 4; ni++) {
            #pragma unroll
            for (int j = 0; j < 2; j++) {
                float s = vsum[ni][j], q = vsq[ni][j];
                #pragma unroll
                for (int st = 4; st < 32; st <<= 1) {
                    s += __shfl_xor_sync(0xFFFFFFFFu, s, st);
                    q += __shfl_xor_sync(0xFFFFFFFFu, q, st);
                }
                if (lane < 4) {
                    int c = col0 + wn + ni*8 + lane*2 + j;
                    atomicAdd(&stats[c], s);
                    atomicAdd(&stats[FEAT + c], q);
                }
            }
        }
    }
}

// ---------------- BatchNorm (apply): fp32 in -> fp16 out ----------------
__global__ void k_bnrelu(const float* __restrict__ X, __half* __restrict__ X16,
                         const float* __restrict__ stats,
                         const float* __restrict__ gamma, const float* __restrict__ beta, int M) {
    int i = blockIdx.x*blockDim.x + threadIdx.x;
    if (i >= M*128) return;
    int r = i >> 7, c = (i & 127) * 4;
    float invM = 1.f / (float)M;
    float4 x = *(const float4*)(X + (size_t)r*FEAT + c);
    float xv[4] = {x.x, x.y, x.z, x.w};
    float y[4];
    #pragma unroll
    for (int j = 0; j < 4; j++) {
        int cc = c + j;
        float mean = stats[cc] * invM;
        float var  = stats[FEAT + cc] * invM - mean*mean;
        float v = gamma[cc] * (xv[j] - mean) * rsqrtf(var + EPS) + beta[cc];
        y[j] = v > 0.f ? v : 0.f;
    }
    __half2 p0 = __halves2half2(__float2half_rn(y[0]), __float2half_rn(y[1]));
    __half2 p1 = __halves2half2(__float2half_rn(y[2]), __float2half_rn(y[3]));
    *(__half2*)(X16 + (size_t)r*FEAT + c)     = p0;
    *(__half2*)(X16 + (size_t)r*FEAT + c + 2) = p1;
}

// ---------------- host ----------------
static void* sym(const void* s) { void* p = nullptr; cudaGetSymbolAddress(&p, s); return p; }

struct StreamCtx {
    cudaStream_t s1;
    cudaEvent_t ev[10];
    bool ok;
    StreamCtx() {
        ok = (cudaStreamCreateWithFlags(&s1, cudaStreamNonBlocking) == cudaSuccess);
        for (int i = 0; i < 10; i++)
            if (cudaEventCreateWithFlags(&ev[i], cudaEventDisableTiming) != cudaSuccess) ok = false;
    }
};

enum { E_START=0, E_X16, E_M1, E_PSELF, E_BND0, E_BNP0, E_M0P, E_M1P, E_PSELF1, E_S1 };

extern "C" void kernel_launch(void* const* d_in, const int* in_sizes, int n_in,
                              void* d_out, int out_size)
{
    static StreamCtx ctx;

    const float* h_d  = (const float*)d_in[0];
    const float* h_p  = (const float*)d_in[1];
    const float* Ws1  = (const float*)d_in[2];
    const float* Wn1  = (const float*)d_in[3];
    const float* b1   = (const float*)d_in[4];
    const float* Ws2  = (const float*)d_in[5];
    const float* Wn2  = (const float*)d_in[6];
    const float* b2   = (const float*)d_in[7];
    const float* gam  = (const float*)d_in[8];
    const float* bet  = (const float*)d_in[9];
    const float* pWd  = (const float*)d_in[10];
    const float* pbd  = (const float*)d_in[11];
    const float* pWp  = (const float*)d_in[12];
    const float* pbp  = (const float*)d_in[13];
    const int*  a_src = (const int*)d_in[14];
    const int*  a_dst = (const int*)d_in[15];
    const int*  i_src = (const int*)d_in[16];
    const int*  i_dst = (const int*)d_in[17];
    float* out = (float*)d_out;
    const int e = in_sizes[14];

    float* xd    = (float*)sym(g_x);
    float* xp    = xd + (size_t)NN*FEAT;
    __half* h16d = (__half*)sym(g_h16);
    __half* h16p = h16d + (size_t)NN*FEAT;
    __half* m16  = (__half*)sym(g_m16);
    __half* m0   = m16;
    __half* m1   = m16 + 1*(size_t)NN*FEAT;
    __half* m2   = m16 + 2*(size_t)NN*FEAT;
    __half* m3   = m16 + 3*(size_t)NN*FEAT;
    __half* w16  = (__half*)sym(g_w16);
    auto W = [&](int slot) { return w16 + (size_t)slot * FF; };
    float* bsum0 = (float*)sym(g_bsum);
    float* bsum1 = bsum0 + FEAT;
    float* st    = (float*)sym(g_stats);
    float* st0d = st, *st0p = st + 2*FEAT, *st1d = st + 4*FEAT, *st1p = st + 6*FEAT;
    int*   cnt   = (int*)sym(g_cnt);

    cudaFuncSetAttribute(k_mma2, cudaFuncAttributeMaxDynamicSharedMemorySize, SMEM_BYTES);

    const bool ok = ctx.ok;
    cudaStream_t S0 = 0;
    cudaStream_t S1 = ok ? ctx.s1 : (cudaStream_t)0;
    auto rec  = [&](int i, cudaStream_t s) { if (ok) cudaEventRecord(ctx.ev[i], s); };
    auto wait = [&](cudaStream_t s, int i)  { if (ok) cudaStreamWaitEvent(s, ctx.ev[i], 0); };

    int xgrid = (NN*128 + 255)/256;
    int wgrid = (FF + 255)/256;
    dim3 ggrid(4, GY);

    auto gemm = [&](cudaStream_t s, const __half* A0, const __half* W0,
                    const float* bias, float* C, float* stats, int accum,
                    const __half* A1 = nullptr, const __half* W1 = nullptr,
                    const __half* A2 = nullptr, const __half* W2p = nullptr) {
        Segs t; t.n = 1;
        t.a[0] = A0; t.w[0] = W0;
        if (A1) { t.a[t.n] = A1; t.w[t.n] = W1; t.n++; }
        if (A2) { t.a[t.n] = A2; t.w[t.n] = W2p; t.n++; }
        k_mma2<<<ggrid, 256, SMEM_BYTES, s>>>(t, bias, C, stats, NN, accum);
    };

    // fork
    rec(E_START, S0);
    wait(S1, E_START);

    // ---- S0: CSR build ----
    k_zero_int<<<(4*NN + 255)/256, 256, 0, S0>>>(cnt, 4*NN);
    k_count<<<(e + 255)/256, 256, 0, S0>>>(a_src, a_dst, i_src, i_dst, e);
    k_scan<<<4, 1024, 0, S0>>>();
    k_fill<<<(e + 255)/256, 256, 0, S0>>>(a_src, a_dst, i_src, i_dst, e);

    // ---- S1: fp16 input conversions (single launch) ----
    {
        dim3 cg(xgrid, 2);
        k_toF16x2<<<cg, 256, 0, S1>>>(h16p, h_p, h16d, h_d, NN);
    }
    rec(E_X16, S1);

    // ---- S0: layer0 aggregates ----
    wait(S0, E_X16);
    k_aggregate<<<NN, 128, 0, S0>>>(m1, h16p, 1);
    rec(E_M1, S0);
    k_aggregate<<<NN, 128, 0, S0>>>(m0, h16d, 0);
    k_aggregate<<<NN, 128, 0, S0>>>(m2, h16p, 2);
    k_aggregate<<<NN, 128, 0, S0>>>(m3, h16p, 3);

    // ---- S1: weight conversions + stats zero ----
    k_combine16<<<wgrid, 256, 0, S1>>>(W(2), Ws1, b1, bsum0);
    k_combine16<<<wgrid, 256, 0, S1>>>(W(8), Ws2, b2, bsum1);
    {
        WJobs jb;
        jb.src[0] = Ws1 + (size_t)FF;     jb.dst[0] = W(0);
        jb.src[1] = Wn1 + (size_t)FF;     jb.dst[1] = W(1);
        jb.src[2] = Wn1;                  jb.dst[2] = W(3);
        jb.src[3] = Wn1 + 2*(size_t)FF;   jb.dst[3] = W(4);
        jb.src[4] = Wn1 + 3*(size_t)FF;   jb.dst[4] = W(5);
        jb.src[5] = Ws2 + (size_t)FF;     jb.dst[5] = W(6);
        jb.src[6] = Wn2 + (size_t)FF;     jb.dst[6] = W(7);
        jb.src[7] = Wn2;                  jb.dst[7] = W(9);
        jb.src[8] = Wn2 + 2*(size_t)FF;   jb.dst[8] = W(10);
        jb.src[9] = Wn2 + 3*(size_t)FF;   jb.dst[9] = W(11);
        jb.src[10] = pWd;                 jb.dst[10] = W(12);
        jb.src[11] = pWp;                 jb.dst[11] = W(13);
        dim3 wg((FF/2 + 255)/256, 12);
        k_w12<<<wg, 256, 0, S1>>>(jb);
    }
    k_zero_float<<<(8*FEAT + 255)/256, 256, 0, S1>>>(st, 8*FEAT);

    // ---- S1: layer0 self GEMMs ----
    gemm(S1, h16p, W(2), bsum0,     xp, nullptr, 0);         // protein self
    rec(E_PSELF, S1);
    gemm(S1, h16d, W(0), b1 + FEAT, xd, nullptr, 0);         // disease self

    // ---- S1: layer0 disease neigh + BN ----
    wait(S1, E_M1);
    gemm(S1, m1, W(1), nullptr, xd, st0d, 1);
    k_bnrelu<<<xgrid, 256, 0, S1>>>(xd, h16d, st0d, gam + 0*FEAT, bet + 0*FEAT, NN);
    rec(E_BND0, S1);

    // ---- S0: layer0 protein neigh + BN (aggs in-order on S0) ----
    wait(S0, E_PSELF);
    gemm(S0, m0, W(3), nullptr, xp, st0p, 1, m2, W(4), m3, W(5));
    k_bnrelu<<<xgrid, 256, 0, S0>>>(xp, h16p, st0p, gam + 1*FEAT, bet + 1*FEAT, NN);
    rec(E_BNP0, S0);

    // ---- layer1 aggregates ----
    wait(S0, E_BND0);
    k_aggregate<<<NN, 128, 0, S0>>>(m0, h16d, 0);
    rec(E_M0P, S0);
    k_aggregate<<<NN, 128, 0, S0>>>(m2, h16p, 2);
    k_aggregate<<<NN, 128, 0, S0>>>(m3, h16p, 3);

    // ---- S1: layer1 — m1' aggregate, then L1 protein self (fills S1 idle window) ----
    wait(S1, E_BNP0);
    k_aggregate<<<NN, 128, 0, S1>>>(m1, h16p, 1);
    rec(E_M1P, S1);
    gemm(S1, h16p, W(8), bsum1, xp, nullptr, 0);             // L1 protein self (xp free after BN_p0)
    rec(E_PSELF1, S1);

    // ---- S1: layer1 disease chain + projection ----
    gemm(S1, h16d, W(6), b2 + FEAT, xd, nullptr, 0);
    gemm(S1, m1,   W(7), nullptr,   xd, st1d, 1);
    wait(S1, E_M0P);                  // h16d WAR: S0's m0' gather must finish before overwrite
    k_bnrelu<<<xgrid, 256, 0, S1>>>(xd, h16d, st1d, gam + 2*FEAT, bet + 2*FEAT, NN);
    gemm(S1, h16d, W(12), pbd, out, nullptr, 0);
    rec(E_S1, S1);

    // ---- S0: layer1 protein neigh + BN + projection ----
    wait(S0, E_PSELF1);               // xp written by pself1 on S1
    gemm(S0, m0,   W(9), nullptr, xp, st1p, 1, m2, W(10), m3, W(11));
    wait(S0, E_M1P);                  // h16p WAR: S1's m1' gather must finish before overwrite
    k_bnrelu<<<xgrid, 256, 0, S0>>>(xp, h16p, st1p, gam + 3*FEAT, bet + 3*FEAT, NN);
    gemm(S0, h16p, W(13), pbp, out + (size_t)NN*FEAT, nullptr, 0);

    // join
    wait(S0, E_S1);
}

// round 17
// speedup vs baseline: 1.5494x; 1.0204x over previous
#include <cuda_runtime.h>
#include <cuda_fp16.h>
#include <cstdint>
#include <cstddef>

#define NN 20000
#define FEAT 512
#define FF (FEAT*FEAT)
#define EE 320000
#define EPS 1e-5f
#define GY ((NN + 127) / 128)

// ---------------- scratch (device globals; no allocation allowed) ----------------
__device__ float  g_x[2][NN*FEAT];                 // fp32 GEMM outputs (BN input)
__device__ __half g_h16[2][(size_t)NN*FEAT];       // fp16 node feats (GEMM A + gather source)
__device__ __half g_m16[4][(size_t)NN*FEAT];       // fp16 aggregate means
__device__ __half g_w16[14][(size_t)FF];           // fp16 weights
__device__ float  g_bsum[2][FEAT];
__device__ float  g_stats[8*FEAT];
__device__ int    g_cnt[4][NN];
__device__ int    g_off[4][NN+1];
__device__ int    g_cur[4][NN];
__device__ int    g_srcid[4][EE];

// ---------------- small utils ----------------
__global__ void k_zero_int(int* p, int n) {
    int i = blockIdx.x*blockDim.x + threadIdx.x;
    if (i < n) p[i] = 0;
}
__global__ void k_zero_float(float* p, int n) {
    int i = blockIdx.x*blockDim.x + threadIdx.x;
    if (i < n) p[i] = 0.f;
}

// ---------------- CSR build ----------------
__global__ void k_count(const int* __restrict__ a_src, const int* __restrict__ a_dst,
                        const int* __restrict__ i_src, const int* __restrict__ i_dst, int e) {
    int idx = blockIdx.x*blockDim.x + threadIdx.x;
    if (idx >= e) return;
    atomicAdd(&g_cnt[0][a_dst[idx]], 1);
    atomicAdd(&g_cnt[1][a_src[idx]], 1);
    atomicAdd(&g_cnt[2][i_dst[idx]], 1);
    atomicAdd(&g_cnt[3][i_src[idx]], 1);
}

// one block per relation; warp-shuffle two-level scan (2 barriers total)
#define SCAN_PER 20   // ceil(20000/1024)
__global__ void k_scan() {
    int r = blockIdx.x;
    int t = threadIdx.x;                 // 0..1023
    int lane = t & 31, wid = t >> 5;
    int base = t * SCAN_PER;
    int loc[SCAN_PER];
    int sum = 0;
    #pragma unroll
    for (int i = 0; i < SCAN_PER; i++) {
        int idx = base + i;
        int c = (idx < NN) ? g_cnt[r][idx] : 0;
        loc[i] = sum;
        sum += c;
    }
    int v = sum;
    #pragma unroll
    for (int d = 1; d < 32; d <<= 1) {
        int u = __shfl_up_sync(0xFFFFFFFFu, v, d);
        if (lane >= d) v += u;
    }
    __shared__ int wsum[32];
    if (lane == 31) wsum[wid] = v;
    __syncthreads();
    if (wid == 0) {
        int w = wsum[lane];
        #pragma unroll
        for (int d = 1; d < 32; d <<= 1) {
            int u = __shfl_up_sync(0xFFFFFFFFu, w, d);
            if (lane >= d) w += u;
        }
        wsum[lane] = w;
    }
    __syncthreads();
    int warpoff = (wid == 0) ? 0 : wsum[wid - 1];
    int excl = warpoff + v - sum;
    #pragma unroll
    for (int i = 0; i < SCAN_PER; i++) {
        int idx = base + i;
        if (idx < NN) {
            int o = excl + loc[i];
            g_off[r][idx] = o;
            g_cur[r][idx] = o;
        }
    }
    if (t == 1023) g_off[r][NN] = excl + sum;
}

__global__ void k_fill(const int* __restrict__ a_src, const int* __restrict__ a_dst,
                       const int* __restrict__ i_src, const int* __restrict__ i_dst, int e) {
    int idx = blockIdx.x*blockDim.x + threadIdx.x;
    if (idx >= e) return;
    int p;
    p = atomicAdd(&g_cur[0][a_dst[idx]], 1); g_srcid[0][p] = a_src[idx];
    p = atomicAdd(&g_cur[1][a_src[idx]], 1); g_srcid[1][p] = a_dst[idx];
    p = atomicAdd(&g_cur[2][i_dst[idx]], 1); g_srcid[2][p] = i_src[idx];
    p = atomicAdd(&g_cur[3][i_src[idx]], 1); g_srcid[3][p] = i_dst[idx];
}

// ---------------- conversions ----------------
// grid.y = which tensor (0: p, 1: d)
__global__ void k_toF16x2(__half* __restrict__ d0, const float* __restrict__ s0,
                          __half* __restrict__ d1, const float* __restrict__ s1, int M) {
    __half* dst = blockIdx.y ? d1 : d0;
    const float* src = blockIdx.y ? s1 : s0;
    int i = blockIdx.x*blockDim.x + threadIdx.x;
    if (i >= M*128) return;
    int r = i >> 7, c = (i & 127) * 4;
    float4 v = *(const float4*)(src + (size_t)r*FEAT + c);
    __half2 p0 = __halves2half2(__float2half_rn(v.x), __float2half_rn(v.y));
    __half2 p1 = __halves2half2(__float2half_rn(v.z), __float2half_rn(v.w));
    *(__half2*)(dst + (size_t)r*FEAT + c)     = p0;
    *(__half2*)(dst + (size_t)r*FEAT + c + 2) = p1;
}

struct WJobs { const float* src[12]; __half* dst[12]; };
__global__ void k_w12(WJobs jobs) {
    int slot = blockIdx.y;
    int i = blockIdx.x*blockDim.x + threadIdx.x;
    if (i >= FF/2) return;
    const float2 v = *(const float2*)(jobs.src[slot] + 2*(size_t)i);
    __half2 h = __halves2half2(__float2half_rn(v.x), __float2half_rn(v.y));
    *(__half2*)(jobs.dst[slot] + 2*(size_t)i) = h;
}

// Wsum = Ws[0]+Ws[2]+Ws[3] (to fp16); bsum = b[0]+b[2]+b[3]
__global__ void k_combine16(__half* __restrict__ dst,
                            const float* __restrict__ Ws, const float* __restrict__ b,
                            float* __restrict__ bsum) {
    int i = blockIdx.x*blockDim.x + threadIdx.x;
    if (i < FF) {
        float x = Ws[i] + Ws[2*(size_t)FF + i] + Ws[3*(size_t)FF + i];
        dst[i] = __float2half_rn(x);
    }
    if (i < FEAT) bsum[i] = b[i] + b[2*FEAT + i] + b[3*FEAT + i];
}

// ---------------- aggregation (fp16 gather, fp32 accumulate, fp16 out) ----------------
__global__ void k_aggregate(__half* __restrict__ outh, const __half* __restrict__ hsrc, int rel) {
    int node = blockIdx.x;
    int t = threadIdx.x;  // 0..127
    int beg = g_off[rel][node];
    int end = g_off[rel][node+1];
    float ax = 0.f, ay = 0.f, az = 0.f, aw = 0.f;
    for (int j = beg; j < end; j++) {
        int s = g_srcid[rel][j];
        uint2 v = __ldg((const uint2*)(hsrc + (size_t)s*FEAT) + t);
        __half2 h0 = *(__half2*)&v.x;
        __half2 h1 = *(__half2*)&v.y;
        float2 f0 = __half22float2(h0);
        float2 f1 = __half22float2(h1);
        ax += f0.x; ay += f0.y; az += f1.x; aw += f1.y;
    }
    float inv = (end > beg) ? 1.f / (float)(end - beg) : 0.f;
    __half2 p0 = __halves2half2(__float2half_rn(ax*inv), __float2half_rn(ay*inv));
    __half2 p1 = __halves2half2(__float2half_rn(az*inv), __float2half_rn(aw*inv));
    size_t base = (size_t)node*FEAT + t*4;
    *(__half2*)(outh + base)     = p0;
    *(__half2*)(outh + base + 2) = p1;
}

// ---------------- fp16 tensor-core GEMM (multi-segment, 3-stage pipeline) ----------------
struct Segs {
    const __half* a[4];
    const __half* w[4];
    int n;
};

__device__ __forceinline__ uint32_t sptr(const void* p) {
    return (uint32_t)__cvta_generic_to_shared(p);
}
__device__ __forceinline__ void cpa16(uint32_t sa, const void* g, bool pred) {
    int sz = pred ? 16 : 0;
    asm volatile("cp.async.cg.shared.global [%0], [%1], 16, %2;\n" :: "r"(sa), "l"(g), "r"(sz));
}

#define APAD 40
#define BPAD 136
#define A_ELEMS (128*APAD)
#define B_ELEMS (32*BPAD)
#define STG_ELEMS (A_ELEMS + B_ELEMS)
#define OFF_A(buf) ((buf)*STG_ELEMS)
#define OFF_B(buf) ((buf)*STG_ELEMS + A_ELEMS)
#define SMEM_ELEMS (3*STG_ELEMS)
#define SMEM_BYTES (SMEM_ELEMS*2)

__global__ __launch_bounds__(256)
void k_mma2(const Segs segs, const float* __restrict__ bias, float* __restrict__ C,
            float* __restrict__ stats, int M, int accum)
{
    extern __shared__ __align__(16) __half sm[];

    const int tid  = threadIdx.x;
    const int lane = tid & 31;
    const int warp = tid >> 5;
    const int wm = (warp & 1) * 64;      // 2 warps along M
    const int wn = (warp >> 1) * 32;     // 4 warps along N
    const int row0 = blockIdx.y * 128;
    const int col0 = blockIdx.x * 128;

    float acc[4][4][4];
    #pragma unroll
    for (int i = 0; i < 4; i++)
        #pragma unroll
        for (int j = 0; j < 4; j++)
            #pragma unroll
            for (int k = 0; k < 4; k++) acc[i][j][k] = 0.f;

    const int T = segs.n * 16;

    auto issue = [&](int t) {
        int buf = t % 3;
        int s  = t >> 4;
        int k0 = (t & 15) * 32;
        const __half* A = segs.a[s];
        const __half* W = segs.w[s];
        #pragma unroll
        for (int l = 0; l < 2; l++) {
            int idx = tid + l*256;       // 0..511
            int r  = idx >> 2;           // 0..127
            int c  = (idx & 3) * 8;      // 0,8,16,24
            int gr = row0 + r;
            cpa16(sptr(sm + OFF_A(buf) + r*APAD + c), A + (size_t)gr*FEAT + k0 + c, gr < M);
            int br = idx >> 4;           // 0..31
            int bc = (idx & 15) * 8;     // 0..120
            cpa16(sptr(sm + OFF_B(buf) + br*BPAD + bc), W + (size_t)(k0 + br)*512 + col0 + bc, true);
        }
        asm volatile("cp.async.commit_group;\n" ::: "memory");
    };

    issue(0);
    if (T > 1) issue(1);

    const int g2 = lane >> 3, lr = lane & 7;

    for (int t = 0; t < T; t++) {
        int buf = t % 3;
        if (t + 1 < T) asm volatile("cp.async.wait_group 1;\n" ::: "memory");
        else           asm volatile("cp.async.wait_group 0;\n" ::: "memory");
        __syncthreads();
        if (t + 2 < T) issue(t + 2);

        #pragma unroll
        for (int ks = 0; ks < 2; ks++) {
            int arow = wm + (g2 & 1)*8 + lr;
            int acol = ks*16 + (g2 >> 1)*8;
            uint32_t af[4][4];
            #pragma unroll
            for (int mi = 0; mi < 4; mi++) {
                uint32_t ad = sptr(sm + OFF_A(buf) + (arow + mi*16)*APAD + acol);
                asm volatile("ldmatrix.sync.aligned.m8n8.x4.shared.b16 {%0,%1,%2,%3}, [%4];\n"
                    : "=r"(af[mi][0]), "=r"(af[mi][1]), "=r"(af[mi][2]), "=r"(af[mi][3])
                    : "r"(ad));
            }
            int brow = ks*16 + (g2 & 1)*8 + lr;
            uint32_t bf[2][4];
            #pragma unroll
            for (int nj = 0; nj < 2; nj++) {
                int bcol = wn + nj*16 + (g2 >> 1)*8;
                uint32_t bd = sptr(sm + OFF_B(buf) + brow*BPAD + bcol);
                asm volatile("ldmatrix.sync.aligned.m8n8.x4.trans.shared.b16 {%0,%1,%2,%3}, [%4];\n"
                    : "=r"(bf[nj][0]), "=r"(bf[nj][1]), "=r"(bf[nj][2]), "=r"(bf[nj][3])
                    : "r"(bd));
            }
            #pragma unroll
            for (int mi = 0; mi < 4; mi++)
                #pragma unroll
                for (int ni = 0; ni < 4; ni++) {
                    uint32_t b0 = bf[ni >> 1][(ni & 1)*2];
                    uint32_t b1 = bf[ni >> 1][(ni & 1)*2 + 1];
                    asm volatile(
                        "mma.sync.aligned.m16n8k16.row.col.f32.f16.f16.f32 "
                        "{%0,%1,%2,%3}, {%4,%5,%6,%7}, {%8,%9}, {%0,%1,%2,%3};\n"
                        : "+f"(acc[mi][ni][0]), "+f"(acc[mi][ni][1]),
                          "+f"(acc[mi][ni][2]), "+f"(acc[mi][ni][3])
                        : "r"(af[mi][0]), "r"(af[mi][1]), "r"(af[mi][2]), "r"(af[mi][3]),
                          "r"(b0), "r"(b1));
                }
        }
    }

    // epilogue: (accumulate|bias) + store + optional fused column stats
    float vsum[4][2], vsq[4][2];
    #pragma unroll
    for (int ni = 0; ni < 4; ni++) { vsum[ni][0]=vsum[ni][1]=vsq[ni][0]=vsq[ni][1]=0.f; }

    #pragma unroll
    for (int mi = 0; mi < 4; mi++) {
        int gr0 = row0 + wm + mi*16 + (lane >> 2);
        int gr1 = gr0 + 8;
        bool p0 = gr0 < M, p1 = gr1 < M;
        #pragma unroll
        for (int ni = 0; ni < 4; ni++) {
            int gc = col0 + wn + ni*8 + (lane & 3)*2;
            float a00 = acc[mi][ni][0], a01 = acc[mi][ni][1];
            float a10 = acc[mi][ni][2], a11 = acc[mi][ni][3];
            if (accum) {
                if (p0) {
                    float2 c0 = *(float2*)(C + (size_t)gr0*FEAT + gc);
                    a00 += c0.x; a01 += c0.y;
                }
                if (p1) {
                    float2 c1 = *(float2*)(C + (size_t)gr1*FEAT + gc);
                    a10 += c1.x; a11 += c1.y;
                }
            } else {
                float b0 = bias[gc], b1 = bias[gc+1];
                a00 += b0; a01 += b1; a10 += b0; a11 += b1;
            }
            if (p0) {
                float2 o; o.x = a00; o.y = a01;
                *(float2*)(C + (size_t)gr0*FEAT + gc) = o;
                vsum[ni][0] += a00; vsq[ni][0] += a00*a00;
                vsum[ni][1] += a01; vsq[ni][1] += a01*a01;
            }
            if (p1) {
                float2 o; o.x = a10; o.y = a11;
                *(float2*)(C + (size_t)gr1*FEAT + gc) = o;
                vsum[ni][0] += a10; vsq[ni][0] += a10*a10;
                vsum[ni][1] += a11; vsq[ni][1] += a11*a11;
            }
        }
    }

    if (stats) {
        #pragma unroll
        for (int ni = 0; ni < 4; ni++) {
            #pragma unroll
            for (int j = 0; j < 2; j++) {
                float s = vsum[ni][j], q = vsq[ni][j];
                #pragma unroll
                for (int st = 4; st < 32; st <<= 1) {
                    s += __shfl_xor_sync(0xFFFFFFFFu, s, st);
                    q += __shfl_xor_sync(0xFFFFFFFFu, q, st);
                }
                if (lane < 4) {
                    int c = col0 + wn + ni*8 + lane*2 + j;
                    atomicAdd(&stats[c], s);
                    atomicAdd(&stats[FEAT + c], q);
                }
            }
        }
    }
}

// ---------------- BatchNorm (apply): fp32 in -> fp16 out ----------------
__global__ void k_bnrelu(const float* __restrict__ X, __half* __restrict__ X16,
                         const float* __restrict__ stats,
                         const float* __restrict__ gamma, const float* __restrict__ beta, int M) {
    int i = blockIdx.x*blockDim.x + threadIdx.x;
    if (i >= M*128) return;
    int r = i >> 7, c = (i & 127) * 4;
    float invM = 1.f / (float)M;
    float4 x = *(const float4*)(X + (size_t)r*FEAT + c);
    float xv[4] = {x.x, x.y, x.z, x.w};
    float y[4];
    #pragma unroll
    for (int j = 0; j < 4; j++) {
        int cc = c + j;
        float mean = stats[cc] * invM;
        float var  = stats[FEAT + cc] * invM - mean*mean;
        float v = gamma[cc] * (xv[j] - mean) * rsqrtf(var + EPS) + beta[cc];
        y[j] = v > 0.f ? v : 0.f;
    }
    __half2 p0 = __halves2half2(__float2half_rn(y[0]), __float2half_rn(y[1]));
    __half2 p1 = __halves2half2(__float2half_rn(y[2]), __float2half_rn(y[3]));
    *(__half2*)(X16 + (size_t)r*FEAT + c)     = p0;
    *(__half2*)(X16 + (size_t)r*FEAT + c + 2) = p1;
}

// ---------------- host ----------------
static void* sym(const void* s) { void* p = nullptr; cudaGetSymbolAddress(&p, s); return p; }

struct StreamCtx {
    cudaStream_t s1;
    cudaEvent_t ev[10];
    bool ok;
    StreamCtx() {
        ok = (cudaStreamCreateWithFlags(&s1, cudaStreamNonBlocking) == cudaSuccess);
        for (int i = 0; i < 10; i++)
            if (cudaEventCreateWithFlags(&ev[i], cudaEventDisableTiming) != cudaSuccess) ok = false;
    }
};

enum { E_START=0, E_X16, E_M1, E_PSELF, E_BND0, E_BNP0, E_M0P, E_M1P, E_PSELF1, E_S1 };

extern "C" void kernel_launch(void* const* d_in, const int* in_sizes, int n_in,
                              void* d_out, int out_size)
{
    static StreamCtx ctx;

    const float* h_d  = (const float*)d_in[0];
    const float* h_p  = (const float*)d_in[1];
    const float* Ws1  = (const float*)d_in[2];
    const float* Wn1  = (const float*)d_in[3];
    const float* b1   = (const float*)d_in[4];
    const float* Ws2  = (const float*)d_in[5];
    const float* Wn2  = (const float*)d_in[6];
    const float* b2   = (const float*)d_in[7];
    const float* gam  = (const float*)d_in[8];
    const float* bet  = (const float*)d_in[9];
    const float* pWd  = (const float*)d_in[10];
    const float* pbd  = (const float*)d_in[11];
    const float* pWp  = (const float*)d_in[12];
    const float* pbp  = (const float*)d_in[13];
    const int*  a_src = (const int*)d_in[14];
    const int*  a_dst = (const int*)d_in[15];
    const int*  i_src = (const int*)d_in[16];
    const int*  i_dst = (const int*)d_in[17];
    float* out = (float*)d_out;
    const int e = in_sizes[14];

    float* xd    = (float*)sym(g_x);
    float* xp    = xd + (size_t)NN*FEAT;
    __half* h16d = (__half*)sym(g_h16);
    __half* h16p = h16d + (size_t)NN*FEAT;
    __half* m16  = (__half*)sym(g_m16);
    __half* m0   = m16;
    __half* m1   = m16 + 1*(size_t)NN*FEAT;
    __half* m2   = m16 + 2*(size_t)NN*FEAT;
    __half* m3   = m16 + 3*(size_t)NN*FEAT;
    __half* w16  = (__half*)sym(g_w16);
    auto W = [&](int slot) { return w16 + (size_t)slot * FF; };
    float* bsum0 = (float*)sym(g_bsum);
    float* bsum1 = bsum0 + FEAT;
    float* st    = (float*)sym(g_stats);
    float* st0d = st, *st0p = st + 2*FEAT, *st1d = st + 4*FEAT, *st1p = st + 6*FEAT;
    int*   cnt   = (int*)sym(g_cnt);

    cudaFuncSetAttribute(k_mma2, cudaFuncAttributeMaxDynamicSharedMemorySize, SMEM_BYTES);

    const bool ok = ctx.ok;
    cudaStream_t S0 = 0;
    cudaStream_t S1 = ok ? ctx.s1 : (cudaStream_t)0;
    auto rec  = [&](int i, cudaStream_t s) { if (ok) cudaEventRecord(ctx.ev[i], s); };
    auto wait = [&](cudaStream_t s, int i)  { if (ok) cudaStreamWaitEvent(s, ctx.ev[i], 0); };

    int xgrid = (NN*128 + 255)/256;
    int wgrid = (FF + 255)/256;
    dim3 ggrid(4, GY);

    auto gemm = [&](cudaStream_t s, const __half* A0, const __half* W0,
                    const float* bias, float* C, float* stats, int accum,
                    const __half* A1 = nullptr, const __half* W1 = nullptr,
                    const __half* A2 = nullptr, const __half* W2p = nullptr) {
        Segs t; t.n = 1;
        t.a[0] = A0; t.w[0] = W0;
        if (A1) { t.a[t.n] = A1; t.w[t.n] = W1; t.n++; }
        if (A2) { t.a[t.n] = A2; t.w[t.n] = W2p; t.n++; }
        k_mma2<<<ggrid, 256, SMEM_BYTES, s>>>(t, bias, C, stats, NN, accum);
    };

    // fork
    rec(E_START, S0);
    wait(S1, E_START);

    // ---- S0: CSR build ----
    k_zero_int<<<(4*NN + 255)/256, 256, 0, S0>>>(cnt, 4*NN);
    k_count<<<(e + 255)/256, 256, 0, S0>>>(a_src, a_dst, i_src, i_dst, e);
    k_scan<<<4, 1024, 0, S0>>>();
    k_fill<<<(e + 255)/256, 256, 0, S0>>>(a_src, a_dst, i_src, i_dst, e);

    // ---- S1: fp16 input conversions (single launch) ----
    {
        dim3 cg(xgrid, 2);
        k_toF16x2<<<cg, 256, 0, S1>>>(h16p, h_p, h16d, h_d, NN);
    }
    rec(E_X16, S1);

    // ---- S0: layer0 aggregates ----
    wait(S0, E_X16);
    k_aggregate<<<NN, 128, 0, S0>>>(m1, h16p, 1);
    rec(E_M1, S0);
    k_aggregate<<<NN, 128, 0, S0>>>(m0, h16d, 0);
    k_aggregate<<<NN, 128, 0, S0>>>(m2, h16p, 2);
    k_aggregate<<<NN, 128, 0, S0>>>(m3, h16p, 3);

    // ---- S1: weight conversions + stats zero ----
    k_combine16<<<wgrid, 256, 0, S1>>>(W(2), Ws1, b1, bsum0);
    k_combine16<<<wgrid, 256, 0, S1>>>(W(8), Ws2, b2, bsum1);
    {
        WJobs jb;
        jb.src[0] = Ws1 + (size_t)FF;     jb.dst[0] = W(0);
        jb.src[1] = Wn1 + (size_t)FF;     jb.dst[1] = W(1);
        jb.src[2] = Wn1;                  jb.dst[2] = W(3);
        jb.src[3] = Wn1 + 2*(size_t)FF;   jb.dst[3] = W(4);
        jb.src[4] = Wn1 + 3*(size_t)FF;   jb.dst[4] = W(5);
        jb.src[5] = Ws2 + (size_t)FF;     jb.dst[5] = W(6);
        jb.src[6] = Wn2 + (size_t)FF;     jb.dst[6] = W(7);
        jb.src[7] = Wn2;                  jb.dst[7] = W(9);
        jb.src[8] = Wn2 + 2*(size_t)FF;   jb.dst[8] = W(10);
        jb.src[9] = Wn2 + 3*(size_t)FF;   jb.dst[9] = W(11);
        jb.src[10] = pWd;                 jb.dst[10] = W(12);
        jb.src[11] = pWp;                 jb.dst[11] = W(13);
        dim3 wg((FF/2 + 255)/256, 12);
        k_w12<<<wg, 256, 0, S1>>>(jb);
    }
    k_zero_float<<<(8*FEAT + 255)/256, 256, 0, S1>>>(st, 8*FEAT);

    // ---- S1: layer0 self GEMMs ----
    gemm(S1, h16p, W(2), bsum0,     xp, nullptr, 0);         // protein self
    rec(E_PSELF, S1);
    gemm(S1, h16d, W(0), b1 + FEAT, xd, nullptr, 0);         // disease self

    // ---- S1: layer0 disease neigh + BN, then L1 disease self fills window (a) ----
    wait(S1, E_M1);
    gemm(S1, m1, W(1), nullptr, xd, st0d, 1);
    k_bnrelu<<<xgrid, 256, 0, S1>>>(xd, h16d, st0d, gam + 0*FEAT, bet + 0*FEAT, NN);
    rec(E_BND0, S1);
    gemm(S1, h16d, W(6), b2 + FEAT, xd, nullptr, 0);         // L1 disease self (h16d ready, xd free)

    // ---- S0: layer0 protein neigh + BN (aggs in-order on S0) ----
    wait(S0, E_PSELF);
    gemm(S0, m0, W(3), nullptr, xp, st0p, 1, m2, W(4), m3, W(5));
    k_bnrelu<<<xgrid, 256, 0, S0>>>(xp, h16p, st0p, gam + 1*FEAT, bet + 1*FEAT, NN);
    rec(E_BNP0, S0);

    // ---- layer1 aggregates ----
    wait(S0, E_BND0);
    k_aggregate<<<NN, 128, 0, S0>>>(m0, h16d, 0);
    rec(E_M0P, S0);
    k_aggregate<<<NN, 128, 0, S0>>>(m2, h16p, 2);
    k_aggregate<<<NN, 128, 0, S0>>>(m3, h16p, 3);

    // ---- S1: layer1 — m1' aggregate, then L1 protein self ----
    wait(S1, E_BNP0);
    k_aggregate<<<NN, 128, 0, S1>>>(m1, h16p, 1);
    rec(E_M1P, S1);
    gemm(S1, h16p, W(8), bsum1, xp, nullptr, 0);             // L1 protein self (xp free after BN_p0)
    rec(E_PSELF1, S1);

    // ---- S1: layer1 disease chain + projection ----
    gemm(S1, m1,   W(7), nullptr,   xd, st1d, 1);            // dneigh1 (xd has dself1 result)
    wait(S1, E_M0P);                  // h16d WAR: S0's m0' gather must finish before overwrite
    k_bnrelu<<<xgrid, 256, 0, S1>>>(xd, h16d, st1d, gam + 2*FEAT, bet + 2*FEAT, NN);
    gemm(S1, h16d, W(12), pbd, out, nullptr, 0);
    rec(E_S1, S1);

    // ---- S0: layer1 protein neigh + BN + projection ----
    wait(S0, E_PSELF1);               // xp written by pself1 on S1
    gemm(S0, m0,   W(9), nullptr, xp, st1p, 1, m2, W(10), m3, W(11));
    wait(S0, E_M1P);                  // h16p WAR: S1's m1' gather must finish before overwrite
    k_bnrelu<<<xgrid, 256, 0, S0>>>(xp, h16p, st1p, gam + 3*FEAT, bet + 3*FEAT, NN);
    gemm(S0, h16p, W(13), pbp, out + (size_t)NN*FEAT, nullptr, 0);

    // join
    wait(S0, E_S1);
}